// round 2
// baseline (speedup 1.0000x reference)
#include <cuda_runtime.h>

#define MAXP 131072
#define MAXL 16384

// ---------------- device scratch (no allocs allowed) ----------------
__device__ float g_path_state[MAXP * 32];   // [P,32]
__device__ float g_link_state[MAXL * 32];   // [L,32]
__device__ float g_link_agg[MAXL * 32];     // [L,32] segment-sum accumulator
__device__ int   g_off[MAXP + 1];           // CSR offsets per path
__device__ int   g_order[MAXP];             // paths grouped by length
__device__ int   g_hist[256];
__device__ int   g_cnt[256];

// ---------------- math helpers ----------------
__device__ __forceinline__ float sigm_(float x) { return 1.f / (1.f + __expf(-x)); }
__device__ __forceinline__ float tanh_(float x) {
    float t = __expf(2.f * x);
    return 1.f - 2.f / (t + 1.f);
}
__device__ __forceinline__ float selu_(float x) {
    const float sc = 1.0507009873554805f, al = 1.6732632423543772f;
    return x > 0.f ? sc * x : sc * al * (__expf(x) - 1.f);
}

// ---------------- setup kernels ----------------
__global__ void k_init_path(const float* __restrict__ traffic, int nP) {
    int i = blockIdx.x * blockDim.x + threadIdx.x;
    if (i < nP * 32) g_path_state[i] = ((i & 31) == 0) ? traffic[i >> 5] : 0.f;
}
__global__ void k_init_link(const float* __restrict__ cap, int nL) {
    int i = blockIdx.x * blockDim.x + threadIdx.x;
    if (i < nL * 32) g_link_state[i] = ((i & 31) == 0) ? cap[i >> 5] : 0.f;
}
__global__ void k_zero_agg(int n) {
    int i = blockIdx.x * blockDim.x + threadIdx.x;
    if (i < n) g_link_agg[i] = 0.f;
}
__global__ void k_offsets(const int* __restrict__ paths, int E, int nP) {
    int e = blockIdx.x * blockDim.x + threadIdx.x;
    if (e >= E) return;
    int pe = paths[e];
    if (pe < 0 || pe >= nP) return;
    if (e == 0) { g_off[nP] = E; g_off[pe] = 0; }
    else if (paths[e - 1] != pe) g_off[pe] = e;
}
__global__ void k_zero_hist() { g_hist[threadIdx.x] = 0; }
__global__ void k_hist(int nP) {
    int p = blockIdx.x * blockDim.x + threadIdx.x;
    if (p >= nP) return;
    int len = g_off[p + 1] - g_off[p];
    if (len > 255) len = 255;
    if (len < 0) len = 0;
    atomicAdd(&g_hist[len], 1);
}
__global__ void k_scan() {
    if (threadIdx.x == 0) {
        int b = 0;
        for (int i = 0; i < 256; i++) { g_cnt[i] = b; b += g_hist[i]; }
    }
}
__global__ void k_scatter(int nP) {
    int p = blockIdx.x * blockDim.x + threadIdx.x;
    if (p >= nP) return;
    int len = g_off[p + 1] - g_off[p];
    if (len > 255) len = 255;
    if (len < 0) len = 0;
    int pos = atomicAdd(&g_cnt[len], 1);
    if (pos < nP) g_order[pos] = p;
}

// ---------------- GRU step (thread-private column tid of xs/hs) ----------------
// xs/hs are i-major: element i of this thread at [i*128 + tid]  (conflict-free)
__device__ __forceinline__ void gru_step(
    int tid,
    const float* __restrict__ wK, const float* __restrict__ wR,
    const float* __restrict__ b0, const float* __restrict__ b1,
    const float* __restrict__ xs, float* __restrict__ hs)
{
    float az[32], ar[32];
#pragma unroll
    for (int j = 0; j < 32; j++) { az[j] = b0[j] + b1[j]; ar[j] = b0[32 + j] + b1[32 + j]; }
#pragma unroll 4
    for (int i = 0; i < 32; i++) {
        float xi = xs[i * 128 + tid];
        float hi = hs[i * 128 + tid];
        const float* kp = wK + i * 96;
        const float* rp = wR + i * 96;
#pragma unroll
        for (int j = 0; j < 32; j++) {
            az[j] = fmaf(xi, kp[j], az[j]);
            az[j] = fmaf(hi, rp[j], az[j]);
            ar[j] = fmaf(xi, kp[32 + j], ar[j]);
            ar[j] = fmaf(hi, rp[32 + j], ar[j]);
        }
    }
#pragma unroll
    for (int j = 0; j < 32; j++) { az[j] = sigm_(az[j]); ar[j] = sigm_(ar[j]); }

    // hh = tanh( x@Kh + b0h + r * (h@Rh + b1h) )
    float ah[32];
#pragma unroll
    for (int j = 0; j < 32; j++) ah[j] = b1[64 + j];
#pragma unroll 4
    for (int i = 0; i < 32; i++) {
        float hi = hs[i * 128 + tid];
        const float* rp = wR + i * 96 + 64;
#pragma unroll
        for (int j = 0; j < 32; j++) ah[j] = fmaf(hi, rp[j], ah[j]);
    }
#pragma unroll
    for (int j = 0; j < 32; j++) ah[j] = fmaf(ar[j], ah[j], b0[64 + j]);
#pragma unroll 4
    for (int i = 0; i < 32; i++) {
        float xi = xs[i * 128 + tid];
        const float* kp = wK + i * 96 + 64;
#pragma unroll
        for (int j = 0; j < 32; j++) ah[j] = fmaf(xi, kp[j], ah[j]);
    }
#pragma unroll
    for (int j = 0; j < 32; j++) {
        float hold = hs[j * 128 + tid];
        float hh = tanh_(ah[j]);
        hs[j * 128 + tid] = az[j] * hold + (1.f - az[j]) * hh;
    }
}

// smem layout for GRU kernels (floats): wK 3072 | wR 3072 | b0 96 | b1 96 | xs 4096 | hs 4096
#define GRU_SMEM_FLOATS (3072 + 3072 + 96 + 96 + 4096 + 4096)
#define GRU_SMEM_BYTES  (GRU_SMEM_FLOATS * 4)

// ---------------- path scan kernel ----------------
__global__ void __launch_bounds__(128) k_path(
    const int* __restrict__ links,
    const float* __restrict__ K, const float* __restrict__ R, const float* __restrict__ b,
    int nP)
{
    extern __shared__ float sm[];
    float* wK = sm;
    float* wR = sm + 3072;
    float* b0 = sm + 6144;
    float* b1 = sm + 6240;
    float* xs = sm + 6336;
    float* hs = xs + 4096;
    int tid = threadIdx.x;
    for (int i = tid; i < 3072; i += 128) { wK[i] = K[i]; wR[i] = R[i]; }
    if (tid < 96) { b0[tid] = b[tid]; b1[tid] = b[96 + tid]; }

    int idx = blockIdx.x * 128 + tid;
    int p = 0, off = 0, len = 0;
    if (idx < nP) { p = g_order[idx]; off = g_off[p]; len = g_off[p + 1] - off; }
    if (len < 0) len = 0;
    __syncthreads();

    if (idx < nP) {
        const float4* hp = (const float4*)(g_path_state + p * 32);
#pragma unroll
        for (int q = 0; q < 8; q++) {
            float4 v = hp[q];
            hs[(4 * q + 0) * 128 + tid] = v.x;
            hs[(4 * q + 1) * 128 + tid] = v.y;
            hs[(4 * q + 2) * 128 + tid] = v.z;
            hs[(4 * q + 3) * 128 + tid] = v.w;
        }
        for (int s = 0; s < len; s++) {
            int lk = links[off + s];
            const float4* xp = (const float4*)(g_link_state + lk * 32);
#pragma unroll
            for (int q = 0; q < 8; q++) {
                float4 v = xp[q];
                xs[(4 * q + 0) * 128 + tid] = v.x;
                xs[(4 * q + 1) * 128 + tid] = v.y;
                xs[(4 * q + 2) * 128 + tid] = v.z;
                xs[(4 * q + 3) * 128 + tid] = v.w;
            }
            gru_step(tid, wK, wR, b0, b1, xs, hs);
            float* agg = g_link_agg + lk * 32;
#pragma unroll
            for (int j = 0; j < 32; j++) atomicAdd(agg + j, hs[j * 128 + tid]);
        }
        float4* ho = (float4*)(g_path_state + p * 32);
#pragma unroll
        for (int q = 0; q < 8; q++) {
            ho[q] = make_float4(hs[(4 * q + 0) * 128 + tid], hs[(4 * q + 1) * 128 + tid],
                                hs[(4 * q + 2) * 128 + tid], hs[(4 * q + 3) * 128 + tid]);
        }
    }
}

// ---------------- link GRU kernel ----------------
__global__ void __launch_bounds__(128) k_link(
    const float* __restrict__ K, const float* __restrict__ R, const float* __restrict__ b,
    int nL)
{
    extern __shared__ float sm[];
    float* wK = sm;
    float* wR = sm + 3072;
    float* b0 = sm + 6144;
    float* b1 = sm + 6240;
    float* xs = sm + 6336;
    float* hs = xs + 4096;
    int tid = threadIdx.x;
    for (int i = tid; i < 3072; i += 128) { wK[i] = K[i]; wR[i] = R[i]; }
    if (tid < 96) { b0[tid] = b[tid]; b1[tid] = b[96 + tid]; }

    int l = blockIdx.x * 128 + tid;
    __syncthreads();
    if (l < nL) {
        const float4* xp = (const float4*)(g_link_agg + l * 32);
        const float4* hp = (const float4*)(g_link_state + l * 32);
#pragma unroll
        for (int q = 0; q < 8; q++) {
            float4 v = xp[q];
            xs[(4 * q + 0) * 128 + tid] = v.x;
            xs[(4 * q + 1) * 128 + tid] = v.y;
            xs[(4 * q + 2) * 128 + tid] = v.z;
            xs[(4 * q + 3) * 128 + tid] = v.w;
            float4 h = hp[q];
            hs[(4 * q + 0) * 128 + tid] = h.x;
            hs[(4 * q + 1) * 128 + tid] = h.y;
            hs[(4 * q + 2) * 128 + tid] = h.z;
            hs[(4 * q + 3) * 128 + tid] = h.w;
        }
        gru_step(tid, wK, wR, b0, b1, xs, hs);
        float4* ho = (float4*)(g_link_state + l * 32);
#pragma unroll
        for (int q = 0; q < 8; q++) {
            ho[q] = make_float4(hs[(4 * q + 0) * 128 + tid], hs[(4 * q + 1) * 128 + tid],
                                hs[(4 * q + 2) * 128 + tid], hs[(4 * q + 3) * 128 + tid]);
        }
    }
}

// ---------------- readout: selu(ps@W1+b1) -> selu(@W2+b2) -> concat @ Wf ----------------
// 64 paths per block, 256 threads. smem: s_ps[32][68] | s_w[64*256] | s_h[256][68]
#define RO_SPS   (32 * 68)
#define RO_SW    (64 * 256)
#define RO_SH    (256 * 68)
#define RO_SMEM_BYTES ((RO_SPS + RO_SW + RO_SH) * 4)

__global__ void __launch_bounds__(256) k_readout(
    const float* __restrict__ W1, const float* __restrict__ b1v,
    const float* __restrict__ W2, const float* __restrict__ b2v,
    const float* __restrict__ Wf, const float* __restrict__ bfv,
    float* __restrict__ out, int nP)
{
    extern __shared__ float sm[];
    float* s_ps = sm;                 // [k=32][r=68]
    float* s_w  = sm + RO_SPS;        // [k up to 64][c=256]
    float* s_h  = sm + RO_SPS + RO_SW;// [c=256][r=68]

    int tx = threadIdx.x;
    int rg = tx >> 4, cg = tx & 15;
    int r0 = rg * 4;
    int p0 = blockIdx.x * 64;
    int nrows = nP - p0; if (nrows > 64) nrows = 64;

    // stage path_state transposed
    for (int idx = tx; idx < 64 * 32; idx += 256) {
        int r = idx >> 5, k = idx & 31;
        float v = (r < nrows) ? g_path_state[(p0 + r) * 32 + k] : 0.f;
        s_ps[k * 68 + r] = v;
    }
    // stage W1 [32][256]
    for (int idx = tx; idx < 32 * 256 / 4; idx += 256)
        ((float4*)s_w)[idx] = ((const float4*)W1)[idx];
    __syncthreads();

    // H1 = selu(ps @ W1 + b1) ; thread computes rows r0..r0+3, cols cg+16v
    float acc[64];
#pragma unroll
    for (int i = 0; i < 64; i++) acc[i] = 0.f;
    for (int k = 0; k < 32; k++) {
        float4 a = *(const float4*)(s_ps + k * 68 + r0);
        const float* bw = s_w + k * 256 + cg;
#pragma unroll
        for (int v = 0; v < 16; v++) {
            float bb = bw[v * 16];
            acc[v * 4 + 0] = fmaf(a.x, bb, acc[v * 4 + 0]);
            acc[v * 4 + 1] = fmaf(a.y, bb, acc[v * 4 + 1]);
            acc[v * 4 + 2] = fmaf(a.z, bb, acc[v * 4 + 2]);
            acc[v * 4 + 3] = fmaf(a.w, bb, acc[v * 4 + 3]);
        }
    }
#pragma unroll
    for (int v = 0; v < 16; v++) {
        float bb = b1v[cg + v * 16];
#pragma unroll
        for (int u = 0; u < 4; u++) acc[v * 4 + u] = selu_(acc[v * 4 + u] + bb);
    }
    // store H1 transposed
#pragma unroll
    for (int v = 0; v < 16; v++)
        *(float4*)(s_h + (cg + v * 16) * 68 + r0) =
            make_float4(acc[v * 4 + 0], acc[v * 4 + 1], acc[v * 4 + 2], acc[v * 4 + 3]);
    __syncthreads();

    // H2 = selu(H1 @ W2 + b2), K=256 in 4 tiles of 64
    float acc2[64];
#pragma unroll
    for (int i = 0; i < 64; i++) acc2[i] = 0.f;
    for (int kt = 0; kt < 4; kt++) {
        for (int idx = tx; idx < 64 * 256 / 4; idx += 256)
            ((float4*)s_w)[idx] = ((const float4*)(W2 + kt * 64 * 256))[idx];
        __syncthreads();
        for (int kk = 0; kk < 64; kk++) {
            int k = kt * 64 + kk;
            float4 a = *(const float4*)(s_h + k * 68 + r0);
            const float* bw = s_w + kk * 256 + cg;
#pragma unroll
            for (int v = 0; v < 16; v++) {
                float bb = bw[v * 16];
                acc2[v * 4 + 0] = fmaf(a.x, bb, acc2[v * 4 + 0]);
                acc2[v * 4 + 1] = fmaf(a.y, bb, acc2[v * 4 + 1]);
                acc2[v * 4 + 2] = fmaf(a.z, bb, acc2[v * 4 + 2]);
                acc2[v * 4 + 3] = fmaf(a.w, bb, acc2[v * 4 + 3]);
            }
        }
        __syncthreads();
    }
#pragma unroll
    for (int v = 0; v < 16; v++) {
        float bb = b2v[cg + v * 16];
#pragma unroll
        for (int u = 0; u < 4; u++) acc2[v * 4 + u] = selu_(acc2[v * 4 + u] + bb);
    }
    // overwrite s_h with H2 (all H1 reads are done — synced above)
#pragma unroll
    for (int v = 0; v < 16; v++)
        *(float4*)(s_h + (cg + v * 16) * 68 + r0) =
            make_float4(acc2[v * 4 + 0], acc2[v * 4 + 1], acc2[v * 4 + 2], acc2[v * 4 + 3]);
    __syncthreads();

    // pred = concat(H2, ps) @ Wf + bf
    if (tx < 128) {
        int p = tx >> 1, o = tx & 1;
        if (p < nrows) {
            float s = bfv[o];
            for (int i = 0; i < 256; i++) s = fmaf(s_h[i * 68 + p], Wf[i * 2 + o], s);
            for (int j = 0; j < 32; j++)  s = fmaf(s_ps[j * 68 + p], Wf[(256 + j) * 2 + o], s);
            out[(p0 + p) * 2 + o] = s;
        }
    }
}

// ---------------- host ----------------
extern "C" void kernel_launch(void* const* d_in, const int* in_sizes, int n_in,
                              void* d_out, int out_size)
{
    const float* cap     = (const float*)d_in[0];
    const float* traffic = (const float*)d_in[1];
    const int*   links   = (const int*)d_in[2];
    const int*   paths   = (const int*)d_in[3];
    // d_in[4] = seqs (implied by contiguity, unused)

    int nL = in_sizes[0];
    int nP = in_sizes[1];
    int E  = in_sizes[2];
    if (nP > MAXP) nP = MAXP;
    if (nL > MAXL) nL = MAXL;

    // locate weight block robustly: first input (after index arrays) sized 32*96
    int wi = 5;
    for (int i = 3; i < n_in; i++) {
        if (in_sizes[i] == 3072) { wi = i; break; }
    }
    const float* K_link = (const float*)d_in[wi + 0];
    const float* R_link = (const float*)d_in[wi + 1];
    const float* b_link = (const float*)d_in[wi + 2];
    const float* K_path = (const float*)d_in[wi + 3];
    const float* R_path = (const float*)d_in[wi + 4];
    const float* b_path = (const float*)d_in[wi + 5];
    const float* W1     = (const float*)d_in[wi + 6];
    const float* b1v    = (const float*)d_in[wi + 7];
    const float* W2     = (const float*)d_in[wi + 8];
    const float* b2v    = (const float*)d_in[wi + 9];
    const float* Wf     = (const float*)d_in[wi + 10];
    const float* bfv    = (const float*)d_in[wi + 11];
    float* out = (float*)d_out;

    cudaFuncSetAttribute(k_path,    cudaFuncAttributeMaxDynamicSharedMemorySize, GRU_SMEM_BYTES);
    cudaFuncSetAttribute(k_link,    cudaFuncAttributeMaxDynamicSharedMemorySize, GRU_SMEM_BYTES);
    cudaFuncSetAttribute(k_readout, cudaFuncAttributeMaxDynamicSharedMemorySize, RO_SMEM_BYTES);

    k_init_path<<<(nP * 32 + 255) / 256, 256>>>(traffic, nP);
    k_init_link<<<(nL * 32 + 255) / 256, 256>>>(cap, nL);
    k_offsets<<<(E + 255) / 256, 256>>>(paths, E, nP);
    k_zero_hist<<<1, 256>>>();
    k_hist<<<(nP + 255) / 256, 256>>>(nP);
    k_scan<<<1, 32>>>();
    k_scatter<<<(nP + 255) / 256, 256>>>(nP);

    for (int it = 0; it < 4; it++) {
        k_zero_agg<<<(nL * 32 + 255) / 256, 256>>>(nL * 32);
        k_path<<<(nP + 127) / 128, 128, GRU_SMEM_BYTES>>>(links, K_path, R_path, b_path, nP);
        k_link<<<(nL + 127) / 128, 128, GRU_SMEM_BYTES>>>(K_link, R_link, b_link, nL);
    }

    k_readout<<<(nP + 63) / 64, 256, RO_SMEM_BYTES>>>(W1, b1v, W2, b2v, Wf, bfv, out, nP);
}

// round 3
// speedup vs baseline: 1.0485x; 1.0485x over previous
#include <cuda_runtime.h>

#define MAXP 131072
#define MAXL 16384

// ---------------- device scratch ----------------
__device__ float g_path_state[MAXP * 32];   // [P,32]
__device__ float g_link_state[MAXL * 32];   // [L,32]
__device__ float g_link_agg[MAXL * 32];     // [L,32] segment-sum accumulator
__device__ float g_lkf[MAXL * 96];          // per-link projected input: x@K_path + bias-fold
__device__ int   g_off[MAXP + 1];
__device__ int   g_order[MAXP];
__device__ int   g_hist[256];
__device__ int   g_cnt[256];

// ---------------- math helpers ----------------
__device__ __forceinline__ float sigm_(float x) { return 1.f / (1.f + __expf(-x)); }
__device__ __forceinline__ float tanh_(float x) {
    float t = __expf(2.f * x);
    return 1.f - 2.f / (t + 1.f);
}
__device__ __forceinline__ float selu_(float x) {
    const float sc = 1.0507009873554805f, al = 1.6732632423543772f;
    return x > 0.f ? sc * x : sc * al * (__expf(x) - 1.f);
}

// ---------------- fused init (launch 0) ----------------
// path_state, link_state, agg zero, hist zero, and iteration-1 LKf
// (link_state row = [cap,0,...] so x@K_path = cap * K_path[0,:]).
__global__ void k_init_all(const float* __restrict__ cap, const float* __restrict__ traffic,
                           const float* __restrict__ K_path, const float* __restrict__ b_path,
                           int nP, int nL)
{
    int i = blockIdx.x * blockDim.x + threadIdx.x;
    if (i < nP * 32) g_path_state[i] = ((i & 31) == 0) ? traffic[i >> 5] : 0.f;
    if (i < nL * 32) { g_link_state[i] = ((i & 31) == 0) ? cap[i >> 5] : 0.f; g_link_agg[i] = 0.f; }
    if (i < nL * 96) {
        int l = i / 96, j = i - l * 96;
        float fold = (j < 64) ? (b_path[j] + b_path[96 + j]) : b_path[j];
        g_lkf[i] = cap[l] * K_path[j] + fold;
    }
    if (i < 256) g_hist[i] = 0;
}

// ---------------- ordering kernels (launches 1-4) ----------------
__global__ void k_offsets(const int* __restrict__ paths, int E, int nP) {
    int e = blockIdx.x * blockDim.x + threadIdx.x;
    if (e >= E) return;
    int pe = paths[e];
    if (pe < 0 || pe >= nP) return;
    if (e == 0) { g_off[nP] = E; g_off[pe] = 0; }
    else if (paths[e - 1] != pe) g_off[pe] = e;
}
__global__ void k_hist(int nP) {
    int p = blockIdx.x * blockDim.x + threadIdx.x;
    if (p >= nP) return;
    int len = g_off[p + 1] - g_off[p];
    if (len > 255) len = 255;
    if (len < 0) len = 0;
    atomicAdd(&g_hist[len], 1);
}
__global__ void k_scan() {
    if (threadIdx.x == 0) {
        int b = 0;
        for (int i = 0; i < 256; i++) { g_cnt[i] = b; b += g_hist[i]; }
    }
}
__global__ void k_scatter(int nP) {
    int p = blockIdx.x * blockDim.x + threadIdx.x;
    if (p >= nP) return;
    int len = g_off[p + 1] - g_off[p];
    if (len > 255) len = 255;
    if (len < 0) len = 0;
    int pos = atomicAdd(&g_cnt[len], 1);
    if (pos < nP) g_order[pos] = p;
}

// ---------------- path scan kernel (launch 5, 7, 9, 11) ----------------
// h register-resident; x-projection pre-folded in g_lkf (z:0-31 r:32-63 A:64-95,
// z/r include b0+b1, A includes b0h). Per step: 3072 FMA (h@R only).
__global__ void __launch_bounds__(128) k_path(
    const int* __restrict__ links,
    const float* __restrict__ R, const float* __restrict__ b, int nP)
{
    __shared__ float wR[3072];
    __shared__ float sb1h[32];
    int tid = threadIdx.x;
    for (int i = tid; i < 3072; i += 128) wR[i] = R[i];
    if (tid < 32) sb1h[tid] = b[96 + 64 + tid];

    int idx = blockIdx.x * 128 + tid;
    int p = 0, off = 0, len = 0;
    if (idx < nP) { p = g_order[idx]; off = g_off[p]; len = g_off[p + 1] - off; if (len < 0) len = 0; }
    __syncthreads();
    if (idx >= nP) return;

    float h[32];
    {
        const float4* hp = (const float4*)(g_path_state + p * 32);
#pragma unroll
        for (int q = 0; q < 8; q++) {
            float4 v = hp[q];
            h[4 * q] = v.x; h[4 * q + 1] = v.y; h[4 * q + 2] = v.z; h[4 * q + 3] = v.w;
        }
    }

    int lk = (len > 0) ? __ldg(links + off) : 0;
    for (int s = 0; s < len; s++) {
        int lk_next = (s + 1 < len) ? __ldg(links + off + s + 1) : 0;
        const float* Lrow = g_lkf + lk * 96;
        float hn[32];
#pragma unroll
        for (int half = 0; half < 2; half++) {
            const int j0 = half * 16;
            float az[16], ar[16], A[16], B[16];
            // init accumulators by L2-resident gather (latency hidden across warps)
#pragma unroll
            for (int q = 0; q < 4; q++) {
                float4 vz = *(const float4*)(Lrow + j0 + 4 * q);
                az[4 * q] = vz.x; az[4 * q + 1] = vz.y; az[4 * q + 2] = vz.z; az[4 * q + 3] = vz.w;
                float4 vr = *(const float4*)(Lrow + 32 + j0 + 4 * q);
                ar[4 * q] = vr.x; ar[4 * q + 1] = vr.y; ar[4 * q + 2] = vr.z; ar[4 * q + 3] = vr.w;
                float4 va = *(const float4*)(Lrow + 64 + j0 + 4 * q);
                A[4 * q] = va.x; A[4 * q + 1] = va.y; A[4 * q + 2] = va.z; A[4 * q + 3] = va.w;
            }
#pragma unroll
            for (int j = 0; j < 16; j++) B[j] = sb1h[j0 + j];
#pragma unroll 4
            for (int i = 0; i < 32; i++) {
                float hi = h[i];
                const float* w = wR + i * 96 + j0;
#pragma unroll
                for (int j = 0; j < 16; j++) {
                    B[j]  = fmaf(hi, w[64 + j], B[j]);
                    az[j] = fmaf(hi, w[j],      az[j]);
                    ar[j] = fmaf(hi, w[32 + j], ar[j]);
                }
            }
#pragma unroll
            for (int j = 0; j < 16; j++) {
                float z = sigm_(az[j]);
                float r = sigm_(ar[j]);
                float hh = tanh_(A[j] + r * B[j]);
                hn[j0 + j] = z * h[j0 + j] + (1.f - z) * hh;
            }
        }
        float* agg = g_link_agg + lk * 32;
#pragma unroll
        for (int j = 0; j < 32; j++) { h[j] = hn[j]; atomicAdd(agg + j, hn[j]); }
        lk = lk_next;
    }

    float4* ho = (float4*)(g_path_state + p * 32);
#pragma unroll
    for (int q = 0; q < 8; q++)
        ho[q] = make_float4(h[4 * q], h[4 * q + 1], h[4 * q + 2], h[4 * q + 3]);
}

// ---------------- link GRU + agg rezero + next-iter LKf (launch 6, 8, 10, 12) ----------------
__global__ void __launch_bounds__(128) k_link(
    const float* __restrict__ K, const float* __restrict__ R, const float* __restrict__ b,
    const float* __restrict__ K_path, const float* __restrict__ b_path, int nL)
{
    __shared__ float wK[3072], wRR[3072], wKp[3072];
    __shared__ float sb0[96], sb1[96], sfold[96];
    int tid = threadIdx.x;
    for (int i = tid; i < 3072; i += 128) { wK[i] = K[i]; wRR[i] = R[i]; wKp[i] = K_path[i]; }
    if (tid < 96) {
        sb0[tid] = b[tid]; sb1[tid] = b[96 + tid];
        sfold[tid] = (tid < 64) ? (b_path[tid] + b_path[96 + tid]) : b_path[tid];
    }
    int l = blockIdx.x * 128 + tid;
    __syncthreads();
    if (l >= nL) return;

    float x[32], h[32];
    {
        const float4* xp = (const float4*)(g_link_agg + l * 32);
        const float4* hp = (const float4*)(g_link_state + l * 32);
#pragma unroll
        for (int q = 0; q < 8; q++) {
            float4 v = xp[q];
            x[4 * q] = v.x; x[4 * q + 1] = v.y; x[4 * q + 2] = v.z; x[4 * q + 3] = v.w;
            float4 u = hp[q];
            h[4 * q] = u.x; h[4 * q + 1] = u.y; h[4 * q + 2] = u.z; h[4 * q + 3] = u.w;
        }
    }

    float hn[32];
#pragma unroll
    for (int half = 0; half < 2; half++) {
        const int j0 = half * 16;
        float az[16], ar[16], A[16], B[16];
#pragma unroll
        for (int j = 0; j < 16; j++) {
            az[j] = sb0[j0 + j] + sb1[j0 + j];
            ar[j] = sb0[32 + j0 + j] + sb1[32 + j0 + j];
            A[j]  = sb0[64 + j0 + j];
            B[j]  = sb1[64 + j0 + j];
        }
#pragma unroll 4
        for (int i = 0; i < 32; i++) {
            float xi = x[i], hi = h[i];
            const float* wk = wK + i * 96 + j0;
            const float* wr = wRR + i * 96 + j0;
#pragma unroll
            for (int j = 0; j < 16; j++) {
                az[j] = fmaf(xi, wk[j], az[j]);      az[j] = fmaf(hi, wr[j], az[j]);
                ar[j] = fmaf(xi, wk[32 + j], ar[j]); ar[j] = fmaf(hi, wr[32 + j], ar[j]);
                A[j]  = fmaf(xi, wk[64 + j], A[j]);  B[j]  = fmaf(hi, wr[64 + j], B[j]);
            }
        }
#pragma unroll
        for (int j = 0; j < 16; j++) {
            float z = sigm_(az[j]);
            float r = sigm_(ar[j]);
            float hh = tanh_(A[j] + r * B[j]);
            hn[j0 + j] = z * h[j0 + j] + (1.f - z) * hh;
        }
    }

    // write new link_state, rezero agg for next iteration
    {
        float4* ho = (float4*)(g_link_state + l * 32);
        float4* ao = (float4*)(g_link_agg + l * 32);
#pragma unroll
        for (int q = 0; q < 8; q++) {
            ho[q] = make_float4(hn[4 * q], hn[4 * q + 1], hn[4 * q + 2], hn[4 * q + 3]);
            ao[q] = make_float4(0.f, 0.f, 0.f, 0.f);
        }
    }

    // next-iteration LKf = hn @ K_path + bias-fold
    float* Lout = g_lkf + l * 96;
#pragma unroll
    for (int c = 0; c < 6; c++) {
        float acc[16];
#pragma unroll
        for (int j = 0; j < 16; j++) acc[j] = sfold[c * 16 + j];
#pragma unroll 4
        for (int i = 0; i < 32; i++) {
            float hi = hn[i];
            const float* w = wKp + i * 96 + c * 16;
#pragma unroll
            for (int j = 0; j < 16; j++) acc[j] = fmaf(hi, w[j], acc[j]);
        }
#pragma unroll
        for (int q = 0; q < 4; q++)
            *(float4*)(Lout + c * 16 + 4 * q) =
                make_float4(acc[4 * q], acc[4 * q + 1], acc[4 * q + 2], acc[4 * q + 3]);
    }
}

// ---------------- readout (launch 13) ----------------
#define RO_SPS   (32 * 68)
#define RO_SW    (64 * 256)
#define RO_SH    (256 * 68)
#define RO_SMEM_BYTES ((RO_SPS + RO_SW + RO_SH) * 4)

__global__ void __launch_bounds__(256) k_readout(
    const float* __restrict__ W1, const float* __restrict__ b1v,
    const float* __restrict__ W2, const float* __restrict__ b2v,
    const float* __restrict__ Wf, const float* __restrict__ bfv,
    float* __restrict__ out, int nP)
{
    extern __shared__ float sm[];
    float* s_ps = sm;
    float* s_w  = sm + RO_SPS;
    float* s_h  = sm + RO_SPS + RO_SW;

    int tx = threadIdx.x;
    int rg = tx >> 4, cg = tx & 15;
    int r0 = rg * 4;
    int p0 = blockIdx.x * 64;
    int nrows = nP - p0; if (nrows > 64) nrows = 64;

    for (int idx = tx; idx < 64 * 32; idx += 256) {
        int r = idx >> 5, k = idx & 31;
        float v = (r < nrows) ? g_path_state[(p0 + r) * 32 + k] : 0.f;
        s_ps[k * 68 + r] = v;
    }
    for (int idx = tx; idx < 32 * 256 / 4; idx += 256)
        ((float4*)s_w)[idx] = ((const float4*)W1)[idx];
    __syncthreads();

    float acc[64];
#pragma unroll
    for (int i = 0; i < 64; i++) acc[i] = 0.f;
    for (int k = 0; k < 32; k++) {
        float4 a = *(const float4*)(s_ps + k * 68 + r0);
        const float* bw = s_w + k * 256 + cg;
#pragma unroll
        for (int v = 0; v < 16; v++) {
            float bb = bw[v * 16];
            acc[v * 4 + 0] = fmaf(a.x, bb, acc[v * 4 + 0]);
            acc[v * 4 + 1] = fmaf(a.y, bb, acc[v * 4 + 1]);
            acc[v * 4 + 2] = fmaf(a.z, bb, acc[v * 4 + 2]);
            acc[v * 4 + 3] = fmaf(a.w, bb, acc[v * 4 + 3]);
        }
    }
#pragma unroll
    for (int v = 0; v < 16; v++) {
        float bb = b1v[cg + v * 16];
#pragma unroll
        for (int u = 0; u < 4; u++) acc[v * 4 + u] = selu_(acc[v * 4 + u] + bb);
    }
#pragma unroll
    for (int v = 0; v < 16; v++)
        *(float4*)(s_h + (cg + v * 16) * 68 + r0) =
            make_float4(acc[v * 4 + 0], acc[v * 4 + 1], acc[v * 4 + 2], acc[v * 4 + 3]);
    __syncthreads();

    float acc2[64];
#pragma unroll
    for (int i = 0; i < 64; i++) acc2[i] = 0.f;
    for (int kt = 0; kt < 4; kt++) {
        for (int idx = tx; idx < 64 * 256 / 4; idx += 256)
            ((float4*)s_w)[idx] = ((const float4*)(W2 + kt * 64 * 256))[idx];
        __syncthreads();
        for (int kk = 0; kk < 64; kk++) {
            int k = kt * 64 + kk;
            float4 a = *(const float4*)(s_h + k * 68 + r0);
            const float* bw = s_w + kk * 256 + cg;
#pragma unroll
            for (int v = 0; v < 16; v++) {
                float bb = bw[v * 16];
                acc2[v * 4 + 0] = fmaf(a.x, bb, acc2[v * 4 + 0]);
                acc2[v * 4 + 1] = fmaf(a.y, bb, acc2[v * 4 + 1]);
                acc2[v * 4 + 2] = fmaf(a.z, bb, acc2[v * 4 + 2]);
                acc2[v * 4 + 3] = fmaf(a.w, bb, acc2[v * 4 + 3]);
            }
        }
        __syncthreads();
    }
#pragma unroll
    for (int v = 0; v < 16; v++) {
        float bb = b2v[cg + v * 16];
#pragma unroll
        for (int u = 0; u < 4; u++) acc2[v * 4 + u] = selu_(acc2[v * 4 + u] + bb);
    }
#pragma unroll
    for (int v = 0; v < 16; v++)
        *(float4*)(s_h + (cg + v * 16) * 68 + r0) =
            make_float4(acc2[v * 4 + 0], acc2[v * 4 + 1], acc2[v * 4 + 2], acc2[v * 4 + 3]);
    __syncthreads();

    if (tx < 128) {
        int p = tx >> 1, o = tx & 1;
        if (p < nrows) {
            float s = bfv[o];
            for (int i = 0; i < 256; i++) s = fmaf(s_h[i * 68 + p], Wf[i * 2 + o], s);
            for (int j = 0; j < 32; j++)  s = fmaf(s_ps[j * 68 + p], Wf[(256 + j) * 2 + o], s);
            out[(p0 + p) * 2 + o] = s;
        }
    }
}

// ---------------- host ----------------
extern "C" void kernel_launch(void* const* d_in, const int* in_sizes, int n_in,
                              void* d_out, int out_size)
{
    const float* cap     = (const float*)d_in[0];
    const float* traffic = (const float*)d_in[1];
    const int*   links   = (const int*)d_in[2];
    const int*   paths   = (const int*)d_in[3];

    int nL = in_sizes[0];
    int nP = in_sizes[1];
    int E  = in_sizes[2];
    if (nP > MAXP) nP = MAXP;
    if (nL > MAXL) nL = MAXL;

    int wi = 5;
    for (int i = 3; i < n_in; i++) {
        if (in_sizes[i] == 3072) { wi = i; break; }
    }
    const float* K_link = (const float*)d_in[wi + 0];
    const float* R_link = (const float*)d_in[wi + 1];
    const float* b_link = (const float*)d_in[wi + 2];
    const float* K_path = (const float*)d_in[wi + 3];
    const float* R_path = (const float*)d_in[wi + 4];
    const float* b_path = (const float*)d_in[wi + 5];
    const float* W1     = (const float*)d_in[wi + 6];
    const float* b1v    = (const float*)d_in[wi + 7];
    const float* W2     = (const float*)d_in[wi + 8];
    const float* b2v    = (const float*)d_in[wi + 9];
    const float* Wf     = (const float*)d_in[wi + 10];
    const float* bfv    = (const float*)d_in[wi + 11];
    float* out = (float*)d_out;

    cudaFuncSetAttribute(k_readout, cudaFuncAttributeMaxDynamicSharedMemorySize, RO_SMEM_BYTES);

    // launches 0-4: init + ordering
    k_init_all<<<(nP * 32 + 255) / 256, 256>>>(cap, traffic, K_path, b_path, nP, nL);
    k_offsets<<<(E + 255) / 256, 256>>>(paths, E, nP);
    k_hist<<<(nP + 255) / 256, 256>>>(nP);
    k_scan<<<1, 32>>>();
    k_scatter<<<(nP + 255) / 256, 256>>>(nP);

    // launches 5-12: T=4 message-passing iterations (launch 5 = first k_path, ncu target)
    for (int it = 0; it < 4; it++) {
        k_path<<<(nP + 127) / 128, 128>>>(links, R_path, b_path, nP);
        k_link<<<(nL + 127) / 128, 128>>>(K_link, R_link, b_link, K_path, b_path, nL);
    }

    // launch 13: readout
    k_readout<<<(nP + 63) / 64, 256, RO_SMEM_BYTES>>>(W1, b1v, W2, b2v, Wf, bfv, out, nP);
}

// round 4
// speedup vs baseline: 1.3351x; 1.2734x over previous
#include <cuda_runtime.h>

#define MAXP 131072
#define MAXL 16384

// ---------------- device scratch ----------------
__device__ float g_path_state[MAXP * 32];   // [P,32]
__device__ float g_link_state[MAXL * 32];   // [L,32]
__device__ float g_link_agg[MAXL * 32];     // [L,32] segment-sum accumulator
__device__ float g_lkf[MAXL * 96];          // per-link projected input (z|r|A), biases folded
__device__ int   g_off[MAXP + 1];
__device__ int   g_order[MAXP];

// ---------------- math helpers ----------------
__device__ __forceinline__ float sigm_(float x) { return 1.f / (1.f + __expf(-x)); }
__device__ __forceinline__ float tanh_(float x) {
    float t = __expf(2.f * x);
    return 1.f - 2.f / (t + 1.f);
}
__device__ __forceinline__ float selu_(float x) {
    const float sc = 1.0507009873554805f, al = 1.6732632423543772f;
    return x > 0.f ? sc * x : sc * al * (__expf(x) - 1.f);
}
__device__ __forceinline__ void redv4(float* gp, float a, float b, float c, float d) {
    asm volatile("red.global.add.v4.f32 [%0], {%1, %2, %3, %4};"
                 :: "l"(gp), "f"(a), "f"(b), "f"(c), "f"(d) : "memory");
}

// ---------------- launch 0: fused init ----------------
__global__ void k_init_all(const float* __restrict__ cap, const float* __restrict__ traffic,
                           const float* __restrict__ K_path, const float* __restrict__ b_path,
                           int nP, int nL)
{
    int i = blockIdx.x * blockDim.x + threadIdx.x;
    if (i < nP * 32) g_path_state[i] = ((i & 31) == 0) ? traffic[i >> 5] : 0.f;
    if (i < nL * 32) { g_link_state[i] = ((i & 31) == 0) ? cap[i >> 5] : 0.f; g_link_agg[i] = 0.f; }
    if (i < nL * 96) {
        int l = i / 96, j = i - l * 96;
        float fold = (j < 64) ? (b_path[j] + b_path[96 + j]) : b_path[j];
        g_lkf[i] = cap[l] * K_path[j] + fold;
    }
}

// ---------------- launch 1: CSR offsets ----------------
__global__ void k_offsets(const int* __restrict__ paths, int E, int nP) {
    int e = blockIdx.x * blockDim.x + threadIdx.x;
    if (e >= E) return;
    int pe = paths[e];
    if (pe < 0 || pe >= nP) return;
    if (e == 0) { g_off[nP] = E; g_off[pe] = 0; }
    else if (paths[e - 1] != pe) g_off[pe] = e;
}

// ---------------- launch 2: length-bucketed ordering (hist+scan+scatter, 1 block) ----------------
__global__ void __launch_bounds__(1024) k_order_build(int nP) {
    __shared__ int scnt[256];
    int tid = threadIdx.x;
    for (int i = tid; i < 256; i += 1024) scnt[i] = 0;
    __syncthreads();
    for (int p = tid; p < nP; p += 1024) {
        int len = g_off[p + 1] - g_off[p];
        len = min(max(len, 0), 255);
        atomicAdd(&scnt[len], 1);
    }
    __syncthreads();
    if (tid == 0) {
        int b = 0;
        for (int i = 0; i < 256; i++) { int c = scnt[i]; scnt[i] = b; b += c; }
    }
    __syncthreads();
    for (int p = tid; p < nP; p += 1024) {
        int len = g_off[p + 1] - g_off[p];
        len = min(max(len, 0), 255);
        int pos = atomicAdd(&scnt[len], 1);
        if (pos < nP) g_order[pos] = p;
    }
}

// ---------------- launch 3,5,7,9: path scan ----------------
// h register-resident; x-projection pre-folded in g_lkf (z:0-31 r:32-63 A:64-95).
// Per step: 3072 FMA (h@R), float4 weight LDS, v4 global reductions.
__global__ void __launch_bounds__(128) k_path(
    const int* __restrict__ links,
    const float* __restrict__ R, const float* __restrict__ b, int nP)
{
    __shared__ __align__(16) float wR[3072];
    __shared__ __align__(16) float sb1h[32];
    int tid = threadIdx.x;
    for (int i = tid; i < 3072; i += 128) wR[i] = R[i];
    if (tid < 32) sb1h[tid] = b[96 + 64 + tid];

    int idx = blockIdx.x * 128 + tid;
    int p = 0, off = 0, len = 0;
    if (idx < nP) { p = g_order[idx]; off = g_off[p]; len = g_off[p + 1] - off; if (len < 0) len = 0; }
    __syncthreads();
    if (idx >= nP) return;

    float h[32];
    {
        const float4* hp = (const float4*)(g_path_state + p * 32);
#pragma unroll
        for (int q = 0; q < 8; q++) {
            float4 v = hp[q];
            h[4 * q] = v.x; h[4 * q + 1] = v.y; h[4 * q + 2] = v.z; h[4 * q + 3] = v.w;
        }
    }

    int lk = (len > 0) ? __ldg(links + off) : 0;
    // warm first row
    {
        const float* Ln = g_lkf + lk * 96;
        asm volatile("prefetch.global.L1 [%0];" :: "l"(Ln));
        asm volatile("prefetch.global.L1 [%0];" :: "l"(Ln + 32));
        asm volatile("prefetch.global.L1 [%0];" :: "l"(Ln + 64));
    }

    for (int s = 0; s < len; s++) {
        int lk_next = (s + 1 < len) ? __ldg(links + off + s + 1) : 0;
        {   // prefetch next step's projected row while we compute
            const float* Ln = g_lkf + lk_next * 96;
            asm volatile("prefetch.global.L1 [%0];" :: "l"(Ln));
            asm volatile("prefetch.global.L1 [%0];" :: "l"(Ln + 32));
            asm volatile("prefetch.global.L1 [%0];" :: "l"(Ln + 64));
        }
        const float* Lrow = g_lkf + lk * 96;
        float hn[32];
#pragma unroll
        for (int half = 0; half < 2; half++) {
            const int j0 = half * 16;
            float az[16], ar[16], A[16], B[16];
#pragma unroll
            for (int q = 0; q < 4; q++) {
                float4 vz = *(const float4*)(Lrow + j0 + 4 * q);
                az[4 * q] = vz.x; az[4 * q + 1] = vz.y; az[4 * q + 2] = vz.z; az[4 * q + 3] = vz.w;
                float4 vr = *(const float4*)(Lrow + 32 + j0 + 4 * q);
                ar[4 * q] = vr.x; ar[4 * q + 1] = vr.y; ar[4 * q + 2] = vr.z; ar[4 * q + 3] = vr.w;
                float4 va = *(const float4*)(Lrow + 64 + j0 + 4 * q);
                A[4 * q] = va.x; A[4 * q + 1] = va.y; A[4 * q + 2] = va.z; A[4 * q + 3] = va.w;
                float4 vb = *(const float4*)(sb1h + j0 + 4 * q);
                B[4 * q] = vb.x; B[4 * q + 1] = vb.y; B[4 * q + 2] = vb.z; B[4 * q + 3] = vb.w;
            }
#pragma unroll 4
            for (int i = 0; i < 32; i++) {
                float hi = h[i];
                const float4* wz = (const float4*)(wR + i * 96 + j0);
                const float4* wr = (const float4*)(wR + i * 96 + 32 + j0);
                const float4* wh = (const float4*)(wR + i * 96 + 64 + j0);
#pragma unroll
                for (int q = 0; q < 4; q++) {
                    float4 a = wz[q];
                    az[4 * q + 0] = fmaf(hi, a.x, az[4 * q + 0]);
                    az[4 * q + 1] = fmaf(hi, a.y, az[4 * q + 1]);
                    az[4 * q + 2] = fmaf(hi, a.z, az[4 * q + 2]);
                    az[4 * q + 3] = fmaf(hi, a.w, az[4 * q + 3]);
                    float4 c = wr[q];
                    ar[4 * q + 0] = fmaf(hi, c.x, ar[4 * q + 0]);
                    ar[4 * q + 1] = fmaf(hi, c.y, ar[4 * q + 1]);
                    ar[4 * q + 2] = fmaf(hi, c.z, ar[4 * q + 2]);
                    ar[4 * q + 3] = fmaf(hi, c.w, ar[4 * q + 3]);
                    float4 d = wh[q];
                    B[4 * q + 0] = fmaf(hi, d.x, B[4 * q + 0]);
                    B[4 * q + 1] = fmaf(hi, d.y, B[4 * q + 1]);
                    B[4 * q + 2] = fmaf(hi, d.z, B[4 * q + 2]);
                    B[4 * q + 3] = fmaf(hi, d.w, B[4 * q + 3]);
                }
            }
#pragma unroll
            for (int j = 0; j < 16; j++) {
                float z = sigm_(az[j]);
                float r = sigm_(ar[j]);
                float hh = tanh_(A[j] + r * B[j]);
                hn[j0 + j] = z * h[j0 + j] + (1.f - z) * hh;
            }
        }
        float* agg = g_link_agg + lk * 32;
#pragma unroll
        for (int q = 0; q < 8; q++)
            redv4(agg + 4 * q, hn[4 * q], hn[4 * q + 1], hn[4 * q + 2], hn[4 * q + 3]);
#pragma unroll
        for (int j = 0; j < 32; j++) h[j] = hn[j];
        lk = lk_next;
    }

    float4* ho = (float4*)(g_path_state + p * 32);
#pragma unroll
    for (int q = 0; q < 8; q++)
        ho[q] = make_float4(h[4 * q], h[4 * q + 1], h[4 * q + 2], h[4 * q + 3]);
}

// ---------------- launch 4,6,8,10: link GRU + agg rezero + next-iter LKf ----------------
__global__ void __launch_bounds__(64) k_link(
    const float* __restrict__ K, const float* __restrict__ R, const float* __restrict__ b,
    const float* __restrict__ K_path, const float* __restrict__ b_path, int nL)
{
    __shared__ __align__(16) float wK[3072], wRR[3072], wKp[3072];
    __shared__ __align__(16) float sb0[96], sb1[96], sfold[96];
    int tid = threadIdx.x;
    for (int i = tid; i < 3072; i += 64) { wK[i] = K[i]; wRR[i] = R[i]; wKp[i] = K_path[i]; }
    for (int i = tid; i < 96; i += 64) {
        sb0[i] = b[i]; sb1[i] = b[96 + i];
        sfold[i] = (i < 64) ? (b_path[i] + b_path[96 + i]) : b_path[i];
    }
    int l = blockIdx.x * 64 + tid;
    __syncthreads();
    if (l >= nL) return;

    float x[32], h[32];
    {
        const float4* xp = (const float4*)(g_link_agg + l * 32);
        const float4* hp = (const float4*)(g_link_state + l * 32);
#pragma unroll
        for (int q = 0; q < 8; q++) {
            float4 v = xp[q];
            x[4 * q] = v.x; x[4 * q + 1] = v.y; x[4 * q + 2] = v.z; x[4 * q + 3] = v.w;
            float4 u = hp[q];
            h[4 * q] = u.x; h[4 * q + 1] = u.y; h[4 * q + 2] = u.z; h[4 * q + 3] = u.w;
        }
    }

    float hn[32];
#pragma unroll
    for (int half = 0; half < 2; half++) {
        const int j0 = half * 16;
        float az[16], ar[16], A[16], B[16];
#pragma unroll
        for (int j = 0; j < 16; j++) {
            az[j] = sb0[j0 + j] + sb1[j0 + j];
            ar[j] = sb0[32 + j0 + j] + sb1[32 + j0 + j];
            A[j]  = sb0[64 + j0 + j];
            B[j]  = sb1[64 + j0 + j];
        }
#pragma unroll 2
        for (int i = 0; i < 32; i++) {
            float xi = x[i], hi = h[i];
            const float4* kz = (const float4*)(wK + i * 96 + j0);
            const float4* kr = (const float4*)(wK + i * 96 + 32 + j0);
            const float4* kh = (const float4*)(wK + i * 96 + 64 + j0);
            const float4* rz = (const float4*)(wRR + i * 96 + j0);
            const float4* rr = (const float4*)(wRR + i * 96 + 32 + j0);
            const float4* rh = (const float4*)(wRR + i * 96 + 64 + j0);
#pragma unroll
            for (int q = 0; q < 4; q++) {
                float4 a = kz[q], c = rz[q];
                az[4 * q + 0] = fmaf(xi, a.x, fmaf(hi, c.x, az[4 * q + 0]));
                az[4 * q + 1] = fmaf(xi, a.y, fmaf(hi, c.y, az[4 * q + 1]));
                az[4 * q + 2] = fmaf(xi, a.z, fmaf(hi, c.z, az[4 * q + 2]));
                az[4 * q + 3] = fmaf(xi, a.w, fmaf(hi, c.w, az[4 * q + 3]));
                float4 d = kr[q], e = rr[q];
                ar[4 * q + 0] = fmaf(xi, d.x, fmaf(hi, e.x, ar[4 * q + 0]));
                ar[4 * q + 1] = fmaf(xi, d.y, fmaf(hi, e.y, ar[4 * q + 1]));
                ar[4 * q + 2] = fmaf(xi, d.z, fmaf(hi, e.z, ar[4 * q + 2]));
                ar[4 * q + 3] = fmaf(xi, d.w, fmaf(hi, e.w, ar[4 * q + 3]));
                float4 f = kh[q], g = rh[q];
                A[4 * q + 0] = fmaf(xi, f.x, A[4 * q + 0]);
                A[4 * q + 1] = fmaf(xi, f.y, A[4 * q + 1]);
                A[4 * q + 2] = fmaf(xi, f.z, A[4 * q + 2]);
                A[4 * q + 3] = fmaf(xi, f.w, A[4 * q + 3]);
                B[4 * q + 0] = fmaf(hi, g.x, B[4 * q + 0]);
                B[4 * q + 1] = fmaf(hi, g.y, B[4 * q + 1]);
                B[4 * q + 2] = fmaf(hi, g.z, B[4 * q + 2]);
                B[4 * q + 3] = fmaf(hi, g.w, B[4 * q + 3]);
            }
        }
#pragma unroll
        for (int j = 0; j < 16; j++) {
            float z = sigm_(az[j]);
            float r = sigm_(ar[j]);
            float hh = tanh_(A[j] + r * B[j]);
            hn[j0 + j] = z * h[j0 + j] + (1.f - z) * hh;
        }
    }

    {
        float4* ho = (float4*)(g_link_state + l * 32);
        float4* ao = (float4*)(g_link_agg + l * 32);
#pragma unroll
        for (int q = 0; q < 8; q++) {
            ho[q] = make_float4(hn[4 * q], hn[4 * q + 1], hn[4 * q + 2], hn[4 * q + 3]);
            ao[q] = make_float4(0.f, 0.f, 0.f, 0.f);
        }
    }

    // next-iteration LKf = hn @ K_path + bias-fold
    float* Lout = g_lkf + l * 96;
#pragma unroll
    for (int c = 0; c < 6; c++) {
        float acc[16];
#pragma unroll
        for (int j = 0; j < 16; j++) acc[j] = sfold[c * 16 + j];
#pragma unroll 4
        for (int i = 0; i < 32; i++) {
            float hi = hn[i];
            const float4* w = (const float4*)(wKp + i * 96 + c * 16);
#pragma unroll
            for (int q = 0; q < 4; q++) {
                float4 a = w[q];
                acc[4 * q + 0] = fmaf(hi, a.x, acc[4 * q + 0]);
                acc[4 * q + 1] = fmaf(hi, a.y, acc[4 * q + 1]);
                acc[4 * q + 2] = fmaf(hi, a.z, acc[4 * q + 2]);
                acc[4 * q + 3] = fmaf(hi, a.w, acc[4 * q + 3]);
            }
        }
#pragma unroll
        for (int q = 0; q < 4; q++)
            *(float4*)(Lout + c * 16 + 4 * q) =
                make_float4(acc[4 * q], acc[4 * q + 1], acc[4 * q + 2], acc[4 * q + 3]);
    }
}

// ---------------- readout (last launch) ----------------
// 64 paths/block, 256 threads. W2 staged in 32-row tiles -> smem 108.5KB -> 2 CTAs/SM.
#define RO_SPS   (32 * 68)
#define RO_SW    (32 * 256)
#define RO_SH    (256 * 68)
#define RO_SMEM_BYTES ((RO_SPS + RO_SW + RO_SH) * 4)

__global__ void __launch_bounds__(256) k_readout(
    const float* __restrict__ W1, const float* __restrict__ b1v,
    const float* __restrict__ W2, const float* __restrict__ b2v,
    const float* __restrict__ Wf, const float* __restrict__ bfv,
    float* __restrict__ out, int nP)
{
    extern __shared__ float sm[];
    float* s_ps = sm;                  // [32][68]
    float* s_w  = sm + RO_SPS;         // [32][256]
    float* s_h  = sm + RO_SPS + RO_SW; // [256][68]

    int tx = threadIdx.x;
    int rg = tx >> 4, cg = tx & 15;
    int r0 = rg * 4;
    int p0 = blockIdx.x * 64;
    int nrows = nP - p0; if (nrows > 64) nrows = 64;

    for (int idx = tx; idx < 64 * 32; idx += 256) {
        int r = idx >> 5, k = idx & 31;
        float v = (r < nrows) ? g_path_state[(p0 + r) * 32 + k] : 0.f;
        s_ps[k * 68 + r] = v;
    }
    for (int idx = tx; idx < 32 * 256 / 4; idx += 256)
        ((float4*)s_w)[idx] = ((const float4*)W1)[idx];
    __syncthreads();

    float acc[64];
#pragma unroll
    for (int i = 0; i < 64; i++) acc[i] = 0.f;
    for (int k = 0; k < 32; k++) {
        float4 a = *(const float4*)(s_ps + k * 68 + r0);
        const float* bw = s_w + k * 256 + cg;
#pragma unroll
        for (int v = 0; v < 16; v++) {
            float bb = bw[v * 16];
            acc[v * 4 + 0] = fmaf(a.x, bb, acc[v * 4 + 0]);
            acc[v * 4 + 1] = fmaf(a.y, bb, acc[v * 4 + 1]);
            acc[v * 4 + 2] = fmaf(a.z, bb, acc[v * 4 + 2]);
            acc[v * 4 + 3] = fmaf(a.w, bb, acc[v * 4 + 3]);
        }
    }
#pragma unroll
    for (int v = 0; v < 16; v++) {
        float bb = b1v[cg + v * 16];
#pragma unroll
        for (int u = 0; u < 4; u++) acc[v * 4 + u] = selu_(acc[v * 4 + u] + bb);
    }
#pragma unroll
    for (int v = 0; v < 16; v++)
        *(float4*)(s_h + (cg + v * 16) * 68 + r0) =
            make_float4(acc[v * 4 + 0], acc[v * 4 + 1], acc[v * 4 + 2], acc[v * 4 + 3]);
    __syncthreads();

    float acc2[64];
#pragma unroll
    for (int i = 0; i < 64; i++) acc2[i] = 0.f;
    for (int kt = 0; kt < 8; kt++) {
        for (int idx = tx; idx < 32 * 256 / 4; idx += 256)
            ((float4*)s_w)[idx] = ((const float4*)(W2 + kt * 32 * 256))[idx];
        __syncthreads();
        for (int kk = 0; kk < 32; kk++) {
            int k = kt * 32 + kk;
            float4 a = *(const float4*)(s_h + k * 68 + r0);
            const float* bw = s_w + kk * 256 + cg;
#pragma unroll
            for (int v = 0; v < 16; v++) {
                float bb = bw[v * 16];
                acc2[v * 4 + 0] = fmaf(a.x, bb, acc2[v * 4 + 0]);
                acc2[v * 4 + 1] = fmaf(a.y, bb, acc2[v * 4 + 1]);
                acc2[v * 4 + 2] = fmaf(a.z, bb, acc2[v * 4 + 2]);
                acc2[v * 4 + 3] = fmaf(a.w, bb, acc2[v * 4 + 3]);
            }
        }
        __syncthreads();
    }
#pragma unroll
    for (int v = 0; v < 16; v++) {
        float bb = b2v[cg + v * 16];
#pragma unroll
        for (int u = 0; u < 4; u++) acc2[v * 4 + u] = selu_(acc2[v * 4 + u] + bb);
    }
#pragma unroll
    for (int v = 0; v < 16; v++)
        *(float4*)(s_h + (cg + v * 16) * 68 + r0) =
            make_float4(acc2[v * 4 + 0], acc2[v * 4 + 1], acc2[v * 4 + 2], acc2[v * 4 + 3]);
    __syncthreads();

    if (tx < 128) {
        int p = tx >> 1, o = tx & 1;
        if (p < nrows) {
            float s = bfv[o];
            for (int i = 0; i < 256; i++) s = fmaf(s_h[i * 68 + p], Wf[i * 2 + o], s);
            for (int j = 0; j < 32; j++)  s = fmaf(s_ps[j * 68 + p], Wf[(256 + j) * 2 + o], s);
            out[(p0 + p) * 2 + o] = s;
        }
    }
}

// ---------------- host ----------------
extern "C" void kernel_launch(void* const* d_in, const int* in_sizes, int n_in,
                              void* d_out, int out_size)
{
    const float* cap     = (const float*)d_in[0];
    const float* traffic = (const float*)d_in[1];
    const int*   links   = (const int*)d_in[2];
    const int*   paths   = (const int*)d_in[3];

    int nL = in_sizes[0];
    int nP = in_sizes[1];
    int E  = in_sizes[2];
    if (nP > MAXP) nP = MAXP;
    if (nL > MAXL) nL = MAXL;

    int wi = 5;
    for (int i = 3; i < n_in; i++) {
        if (in_sizes[i] == 3072) { wi = i; break; }
    }
    const float* K_link = (const float*)d_in[wi + 0];
    const float* R_link = (const float*)d_in[wi + 1];
    const float* b_link = (const float*)d_in[wi + 2];
    const float* K_path = (const float*)d_in[wi + 3];
    const float* R_path = (const float*)d_in[wi + 4];
    const float* b_path = (const float*)d_in[wi + 5];
    const float* W1     = (const float*)d_in[wi + 6];
    const float* b1v    = (const float*)d_in[wi + 7];
    const float* W2     = (const float*)d_in[wi + 8];
    const float* b2v    = (const float*)d_in[wi + 9];
    const float* Wf     = (const float*)d_in[wi + 10];
    const float* bfv    = (const float*)d_in[wi + 11];
    float* out = (float*)d_out;

    cudaFuncSetAttribute(k_readout, cudaFuncAttributeMaxDynamicSharedMemorySize, RO_SMEM_BYTES);

    // launches 0-2: init + ordering  (launch index 3 = first k_path -> ncu target)
    k_init_all<<<(nP * 32 + 255) / 256, 256>>>(cap, traffic, K_path, b_path, nP, nL);
    k_offsets<<<(E + 255) / 256, 256>>>(paths, E, nP);
    k_order_build<<<1, 1024>>>(nP);

    // launches 3-10: T=4 message-passing iterations
    for (int it = 0; it < 4; it++) {
        k_path<<<(nP + 127) / 128, 128>>>(links, R_path, b_path, nP);
        k_link<<<(nL + 63) / 64, 64>>>(K_link, R_link, b_link, K_path, b_path, nL);
    }

    // launch 11: readout
    k_readout<<<(nP + 63) / 64, 256, RO_SMEM_BYTES>>>(W1, b1v, W2, b2v, Wf, bfv, out, nP);
}

// round 5
// speedup vs baseline: 1.6389x; 1.2275x over previous
#include <cuda_runtime.h>

#define MAXP 131072
#define MAXL 16384

// ---------------- device scratch ----------------
__device__ float g_path_state[MAXP * 32];   // [P,32]
__device__ float g_link_state[MAXL * 32];   // [L,32]
__device__ float g_link_agg[MAXL * 32];     // [L,32] segment-sum accumulator
__device__ float g_lkf[MAXL * 96];          // per-link projected input (z|r|A), biases folded
__device__ int   g_off[MAXP + 1];
__device__ int   g_order[MAXP];

// ---------------- math helpers ----------------
__device__ __forceinline__ float tanhapx_(float x) {
    float y;
    asm("tanh.approx.f32 %0, %1;" : "=f"(y) : "f"(x));
    return y;
}
__device__ __forceinline__ float sigm_(float x) {
    return fmaf(0.5f, tanhapx_(0.5f * x), 0.5f);
}
__device__ __forceinline__ float selu_(float x) {
    const float sc = 1.0507009873554805f, al = 1.6732632423543772f;
    return x > 0.f ? sc * x : sc * al * (__expf(x) - 1.f);
}
__device__ __forceinline__ void redv4(float* gp, float a, float b, float c, float d) {
    asm volatile("red.global.add.v4.f32 [%0], {%1, %2, %3, %4};"
                 :: "l"(gp), "f"(a), "f"(b), "f"(c), "f"(d) : "memory");
}

// ---------------- launch 0: fused init ----------------
__global__ void k_init_all(const float* __restrict__ cap, const float* __restrict__ traffic,
                           const float* __restrict__ K_path, const float* __restrict__ b_path,
                           int nP, int nL)
{
    int i = blockIdx.x * blockDim.x + threadIdx.x;
    if (i < nP * 32) g_path_state[i] = ((i & 31) == 0) ? traffic[i >> 5] : 0.f;
    if (i < nL * 32) { g_link_state[i] = ((i & 31) == 0) ? cap[i >> 5] : 0.f; g_link_agg[i] = 0.f; }
    if (i < nL * 96) {
        int l = i / 96, j = i - l * 96;
        float fold = (j < 64) ? (b_path[j] + b_path[96 + j]) : b_path[j];
        g_lkf[i] = cap[l] * K_path[j] + fold;
    }
}

// ---------------- launch 1: CSR offsets ----------------
__global__ void k_offsets(const int* __restrict__ paths, int E, int nP) {
    int e = blockIdx.x * blockDim.x + threadIdx.x;
    if (e >= E) return;
    int pe = paths[e];
    if (pe < 0 || pe >= nP) return;
    if (e == 0) { g_off[nP] = E; g_off[pe] = 0; }
    else if (paths[e - 1] != pe) g_off[pe] = e;
}

// ---------------- launch 2: ordering, LONGEST length first (1 block) ----------------
__global__ void __launch_bounds__(1024) k_order_build(int nP) {
    __shared__ int scnt[256];
    int tid = threadIdx.x;
    for (int i = tid; i < 256; i += 1024) scnt[i] = 0;
    __syncthreads();
    for (int p = tid; p < nP; p += 1024) {
        int len = g_off[p + 1] - g_off[p];
        len = min(max(len, 0), 255);
        atomicAdd(&scnt[len], 1);
    }
    __syncthreads();
    if (tid == 0) {
        int b = 0;
        for (int i = 255; i >= 0; i--) { int c = scnt[i]; scnt[i] = b; b += c; }  // descending
    }
    __syncthreads();
    for (int p = tid; p < nP; p += 1024) {
        int len = g_off[p + 1] - g_off[p];
        len = min(max(len, 0), 255);
        int pos = atomicAdd(&scnt[len], 1);
        if (pos < nP) g_order[pos] = p;
    }
}

// ---------------- launch 3,5,7,9: path scan ----------------
// h register-resident; x-projection pre-folded in g_lkf (z:0-31 r:32-63 A:64-95).
// Gates computed in 4 j-quarters of 8 to cap live registers (-> 4 CTAs/SM).
__global__ void __launch_bounds__(128, 4) k_path(
    const int* __restrict__ links,
    const float* __restrict__ R, const float* __restrict__ b, int nP)
{
    __shared__ __align__(16) float wR[3072];
    __shared__ __align__(16) float sb1h[32];
    int tid = threadIdx.x;
    for (int i = tid; i < 3072; i += 128) wR[i] = R[i];
    if (tid < 32) sb1h[tid] = b[96 + 64 + tid];

    int idx = blockIdx.x * 128 + tid;
    int p = 0, off = 0, len = 0;
    if (idx < nP) { p = g_order[idx]; off = g_off[p]; len = g_off[p + 1] - off; if (len < 0) len = 0; }
    __syncthreads();
    if (idx >= nP) return;

    float h[32];
    {
        const float4* hp = (const float4*)(g_path_state + p * 32);
#pragma unroll
        for (int q = 0; q < 8; q++) {
            float4 v = hp[q];
            h[4 * q] = v.x; h[4 * q + 1] = v.y; h[4 * q + 2] = v.z; h[4 * q + 3] = v.w;
        }
    }

    int lk = (len > 0) ? __ldg(links + off) : 0;
    {
        const float* Ln = g_lkf + lk * 96;
        asm volatile("prefetch.global.L1 [%0];" :: "l"(Ln));
        asm volatile("prefetch.global.L1 [%0];" :: "l"(Ln + 32));
        asm volatile("prefetch.global.L1 [%0];" :: "l"(Ln + 64));
    }

    for (int s = 0; s < len; s++) {
        int lk_next = (s + 1 < len) ? __ldg(links + off + s + 1) : 0;
        {
            const float* Ln = g_lkf + lk_next * 96;
            asm volatile("prefetch.global.L1 [%0];" :: "l"(Ln));
            asm volatile("prefetch.global.L1 [%0];" :: "l"(Ln + 32));
            asm volatile("prefetch.global.L1 [%0];" :: "l"(Ln + 64));
        }
        const float* Lrow = g_lkf + lk * 96;
        float hn[32];
#pragma unroll
        for (int qrt = 0; qrt < 4; qrt++) {
            const int j0 = qrt * 8;
            float az[8], ar[8], A[8], B[8];
#pragma unroll
            for (int q = 0; q < 2; q++) {
                float4 vz = *(const float4*)(Lrow + j0 + 4 * q);
                az[4 * q] = vz.x; az[4 * q + 1] = vz.y; az[4 * q + 2] = vz.z; az[4 * q + 3] = vz.w;
                float4 vr = *(const float4*)(Lrow + 32 + j0 + 4 * q);
                ar[4 * q] = vr.x; ar[4 * q + 1] = vr.y; ar[4 * q + 2] = vr.z; ar[4 * q + 3] = vr.w;
                float4 va = *(const float4*)(Lrow + 64 + j0 + 4 * q);
                A[4 * q] = va.x; A[4 * q + 1] = va.y; A[4 * q + 2] = va.z; A[4 * q + 3] = va.w;
                float4 vb = *(const float4*)(sb1h + j0 + 4 * q);
                B[4 * q] = vb.x; B[4 * q + 1] = vb.y; B[4 * q + 2] = vb.z; B[4 * q + 3] = vb.w;
            }
#pragma unroll 8
            for (int i = 0; i < 32; i++) {
                float hi = h[i];
                const float4* wz = (const float4*)(wR + i * 96 + j0);
                const float4* wr = (const float4*)(wR + i * 96 + 32 + j0);
                const float4* wh = (const float4*)(wR + i * 96 + 64 + j0);
#pragma unroll
                for (int q = 0; q < 2; q++) {
                    float4 a = wz[q];
                    az[4 * q + 0] = fmaf(hi, a.x, az[4 * q + 0]);
                    az[4 * q + 1] = fmaf(hi, a.y, az[4 * q + 1]);
                    az[4 * q + 2] = fmaf(hi, a.z, az[4 * q + 2]);
                    az[4 * q + 3] = fmaf(hi, a.w, az[4 * q + 3]);
                    float4 c = wr[q];
                    ar[4 * q + 0] = fmaf(hi, c.x, ar[4 * q + 0]);
                    ar[4 * q + 1] = fmaf(hi, c.y, ar[4 * q + 1]);
                    ar[4 * q + 2] = fmaf(hi, c.z, ar[4 * q + 2]);
                    ar[4 * q + 3] = fmaf(hi, c.w, ar[4 * q + 3]);
                    float4 d = wh[q];
                    B[4 * q + 0] = fmaf(hi, d.x, B[4 * q + 0]);
                    B[4 * q + 1] = fmaf(hi, d.y, B[4 * q + 1]);
                    B[4 * q + 2] = fmaf(hi, d.z, B[4 * q + 2]);
                    B[4 * q + 3] = fmaf(hi, d.w, B[4 * q + 3]);
                }
            }
#pragma unroll
            for (int j = 0; j < 8; j++) {
                float z = sigm_(az[j]);
                float r = sigm_(ar[j]);
                float hh = tanhapx_(A[j] + r * B[j]);
                hn[j0 + j] = z * h[j0 + j] + (1.f - z) * hh;
            }
        }
        float* agg = g_link_agg + lk * 32;
#pragma unroll
        for (int q = 0; q < 8; q++)
            redv4(agg + 4 * q, hn[4 * q], hn[4 * q + 1], hn[4 * q + 2], hn[4 * q + 3]);
#pragma unroll
        for (int j = 0; j < 32; j++) h[j] = hn[j];
        lk = lk_next;
    }

    float4* ho = (float4*)(g_path_state + p * 32);
#pragma unroll
    for (int q = 0; q < 8; q++)
        ho[q] = make_float4(h[4 * q], h[4 * q + 1], h[4 * q + 2], h[4 * q + 3]);
}

// ---------------- launch 4,6,8,10: link GRU + agg rezero + next-iter LKf ----------------
__global__ void __launch_bounds__(64) k_link(
    const float* __restrict__ K, const float* __restrict__ R, const float* __restrict__ b,
    const float* __restrict__ K_path, const float* __restrict__ b_path, int nL)
{
    __shared__ __align__(16) float wK[3072], wRR[3072], wKp[3072];
    __shared__ __align__(16) float sb0[96], sb1[96], sfold[96];
    int tid = threadIdx.x;
    for (int i = tid; i < 3072; i += 64) { wK[i] = K[i]; wRR[i] = R[i]; wKp[i] = K_path[i]; }
    for (int i = tid; i < 96; i += 64) {
        sb0[i] = b[i]; sb1[i] = b[96 + i];
        sfold[i] = (i < 64) ? (b_path[i] + b_path[96 + i]) : b_path[i];
    }
    int l = blockIdx.x * 64 + tid;
    __syncthreads();
    if (l >= nL) return;

    float x[32], h[32];
    {
        const float4* xp = (const float4*)(g_link_agg + l * 32);
        const float4* hp = (const float4*)(g_link_state + l * 32);
#pragma unroll
        for (int q = 0; q < 8; q++) {
            float4 v = xp[q];
            x[4 * q] = v.x; x[4 * q + 1] = v.y; x[4 * q + 2] = v.z; x[4 * q + 3] = v.w;
            float4 u = hp[q];
            h[4 * q] = u.x; h[4 * q + 1] = u.y; h[4 * q + 2] = u.z; h[4 * q + 3] = u.w;
        }
    }

    float hn[32];
#pragma unroll
    for (int half = 0; half < 2; half++) {
        const int j0 = half * 16;
        float az[16], ar[16], A[16], B[16];
#pragma unroll
        for (int j = 0; j < 16; j++) {
            az[j] = sb0[j0 + j] + sb1[j0 + j];
            ar[j] = sb0[32 + j0 + j] + sb1[32 + j0 + j];
            A[j]  = sb0[64 + j0 + j];
            B[j]  = sb1[64 + j0 + j];
        }
#pragma unroll 2
        for (int i = 0; i < 32; i++) {
            float xi = x[i], hi = h[i];
            const float4* kz = (const float4*)(wK + i * 96 + j0);
            const float4* kr = (const float4*)(wK + i * 96 + 32 + j0);
            const float4* kh = (const float4*)(wK + i * 96 + 64 + j0);
            const float4* rz = (const float4*)(wRR + i * 96 + j0);
            const float4* rr = (const float4*)(wRR + i * 96 + 32 + j0);
            const float4* rh = (const float4*)(wRR + i * 96 + 64 + j0);
#pragma unroll
            for (int q = 0; q < 4; q++) {
                float4 a = kz[q], c = rz[q];
                az[4 * q + 0] = fmaf(xi, a.x, fmaf(hi, c.x, az[4 * q + 0]));
                az[4 * q + 1] = fmaf(xi, a.y, fmaf(hi, c.y, az[4 * q + 1]));
                az[4 * q + 2] = fmaf(xi, a.z, fmaf(hi, c.z, az[4 * q + 2]));
                az[4 * q + 3] = fmaf(xi, a.w, fmaf(hi, c.w, az[4 * q + 3]));
                float4 d = kr[q], e = rr[q];
                ar[4 * q + 0] = fmaf(xi, d.x, fmaf(hi, e.x, ar[4 * q + 0]));
                ar[4 * q + 1] = fmaf(xi, d.y, fmaf(hi, e.y, ar[4 * q + 1]));
                ar[4 * q + 2] = fmaf(xi, d.z, fmaf(hi, e.z, ar[4 * q + 2]));
                ar[4 * q + 3] = fmaf(xi, d.w, fmaf(hi, e.w, ar[4 * q + 3]));
                float4 f = kh[q], g = rh[q];
                A[4 * q + 0] = fmaf(xi, f.x, A[4 * q + 0]);
                A[4 * q + 1] = fmaf(xi, f.y, A[4 * q + 1]);
                A[4 * q + 2] = fmaf(xi, f.z, A[4 * q + 2]);
                A[4 * q + 3] = fmaf(xi, f.w, A[4 * q + 3]);
                B[4 * q + 0] = fmaf(hi, g.x, B[4 * q + 0]);
                B[4 * q + 1] = fmaf(hi, g.y, B[4 * q + 1]);
                B[4 * q + 2] = fmaf(hi, g.z, B[4 * q + 2]);
                B[4 * q + 3] = fmaf(hi, g.w, B[4 * q + 3]);
            }
        }
#pragma unroll
        for (int j = 0; j < 16; j++) {
            float z = sigm_(az[j]);
            float r = sigm_(ar[j]);
            float hh = tanhapx_(A[j] + r * B[j]);
            hn[j0 + j] = z * h[j0 + j] + (1.f - z) * hh;
        }
    }

    {
        float4* ho = (float4*)(g_link_state + l * 32);
        float4* ao = (float4*)(g_link_agg + l * 32);
#pragma unroll
        for (int q = 0; q < 8; q++) {
            ho[q] = make_float4(hn[4 * q], hn[4 * q + 1], hn[4 * q + 2], hn[4 * q + 3]);
            ao[q] = make_float4(0.f, 0.f, 0.f, 0.f);
        }
    }

    // next-iteration LKf = hn @ K_path + bias-fold
    float* Lout = g_lkf + l * 96;
#pragma unroll
    for (int c = 0; c < 6; c++) {
        float acc[16];
#pragma unroll
        for (int j = 0; j < 16; j++) acc[j] = sfold[c * 16 + j];
#pragma unroll 4
        for (int i = 0; i < 32; i++) {
            float hi = hn[i];
            const float4* w = (const float4*)(wKp + i * 96 + c * 16);
#pragma unroll
            for (int q = 0; q < 4; q++) {
                float4 a = w[q];
                acc[4 * q + 0] = fmaf(hi, a.x, acc[4 * q + 0]);
                acc[4 * q + 1] = fmaf(hi, a.y, acc[4 * q + 1]);
                acc[4 * q + 2] = fmaf(hi, a.z, acc[4 * q + 2]);
                acc[4 * q + 3] = fmaf(hi, a.w, acc[4 * q + 3]);
            }
        }
#pragma unroll
        for (int q = 0; q < 4; q++)
            *(float4*)(Lout + c * 16 + 4 * q) =
                make_float4(acc[4 * q], acc[4 * q + 1], acc[4 * q + 2], acc[4 * q + 3]);
    }
}

// ---------------- readout (last launch) ----------------
#define RO_SPS   (32 * 68)
#define RO_SW    (32 * 256)
#define RO_SH    (256 * 68)
#define RO_SMEM_BYTES ((RO_SPS + RO_SW + RO_SH) * 4)

__global__ void __launch_bounds__(256) k_readout(
    const float* __restrict__ W1, const float* __restrict__ b1v,
    const float* __restrict__ W2, const float* __restrict__ b2v,
    const float* __restrict__ Wf, const float* __restrict__ bfv,
    float* __restrict__ out, int nP)
{
    extern __shared__ float sm[];
    float* s_ps = sm;                  // [32][68]
    float* s_w  = sm + RO_SPS;         // [32][256]
    float* s_h  = sm + RO_SPS + RO_SW; // [256][68]

    int tx = threadIdx.x;
    int rg = tx >> 4, cg = tx & 15;
    int r0 = rg * 4;
    int p0 = blockIdx.x * 64;
    int nrows = nP - p0; if (nrows > 64) nrows = 64;

    for (int idx = tx; idx < 64 * 32; idx += 256) {
        int r = idx >> 5, k = idx & 31;
        float v = (r < nrows) ? g_path_state[(p0 + r) * 32 + k] : 0.f;
        s_ps[k * 68 + r] = v;
    }
    for (int idx = tx; idx < 32 * 256 / 4; idx += 256)
        ((float4*)s_w)[idx] = ((const float4*)W1)[idx];
    __syncthreads();

    float acc[64];
#pragma unroll
    for (int i = 0; i < 64; i++) acc[i] = 0.f;
    for (int k = 0; k < 32; k++) {
        float4 a = *(const float4*)(s_ps + k * 68 + r0);
        const float* bw = s_w + k * 256 + cg;
#pragma unroll
        for (int v = 0; v < 16; v++) {
            float bb = bw[v * 16];
            acc[v * 4 + 0] = fmaf(a.x, bb, acc[v * 4 + 0]);
            acc[v * 4 + 1] = fmaf(a.y, bb, acc[v * 4 + 1]);
            acc[v * 4 + 2] = fmaf(a.z, bb, acc[v * 4 + 2]);
            acc[v * 4 + 3] = fmaf(a.w, bb, acc[v * 4 + 3]);
        }
    }
#pragma unroll
    for (int v = 0; v < 16; v++) {
        float bb = b1v[cg + v * 16];
#pragma unroll
        for (int u = 0; u < 4; u++) acc[v * 4 + u] = selu_(acc[v * 4 + u] + bb);
    }
#pragma unroll
    for (int v = 0; v < 16; v++)
        *(float4*)(s_h + (cg + v * 16) * 68 + r0) =
            make_float4(acc[v * 4 + 0], acc[v * 4 + 1], acc[v * 4 + 2], acc[v * 4 + 3]);
    __syncthreads();

    float acc2[64];
#pragma unroll
    for (int i = 0; i < 64; i++) acc2[i] = 0.f;
    for (int kt = 0; kt < 8; kt++) {
        for (int idx = tx; idx < 32 * 256 / 4; idx += 256)
            ((float4*)s_w)[idx] = ((const float4*)(W2 + kt * 32 * 256))[idx];
        __syncthreads();
        for (int kk = 0; kk < 32; kk++) {
            int k = kt * 32 + kk;
            float4 a = *(const float4*)(s_h + k * 68 + r0);
            const float* bw = s_w + kk * 256 + cg;
#pragma unroll
            for (int v = 0; v < 16; v++) {
                float bb = bw[v * 16];
                acc2[v * 4 + 0] = fmaf(a.x, bb, acc2[v * 4 + 0]);
                acc2[v * 4 + 1] = fmaf(a.y, bb, acc2[v * 4 + 1]);
                acc2[v * 4 + 2] = fmaf(a.z, bb, acc2[v * 4 + 2]);
                acc2[v * 4 + 3] = fmaf(a.w, bb, acc2[v * 4 + 3]);
            }
        }
        __syncthreads();
    }
#pragma unroll
    for (int v = 0; v < 16; v++) {
        float bb = b2v[cg + v * 16];
#pragma unroll
        for (int u = 0; u < 4; u++) acc2[v * 4 + u] = selu_(acc2[v * 4 + u] + bb);
    }
#pragma unroll
    for (int v = 0; v < 16; v++)
        *(float4*)(s_h + (cg + v * 16) * 68 + r0) =
            make_float4(acc2[v * 4 + 0], acc2[v * 4 + 1], acc2[v * 4 + 2], acc2[v * 4 + 3]);
    __syncthreads();

    if (tx < 128) {
        int p = tx >> 1, o = tx & 1;
        if (p < nrows) {
            float s = bfv[o];
            for (int i = 0; i < 256; i++) s = fmaf(s_h[i * 68 + p], Wf[i * 2 + o], s);
            for (int j = 0; j < 32; j++)  s = fmaf(s_ps[j * 68 + p], Wf[(256 + j) * 2 + o], s);
            out[(p0 + p) * 2 + o] = s;
        }
    }
}

// ---------------- host ----------------
extern "C" void kernel_launch(void* const* d_in, const int* in_sizes, int n_in,
                              void* d_out, int out_size)
{
    const float* cap     = (const float*)d_in[0];
    const float* traffic = (const float*)d_in[1];
    const int*   links   = (const int*)d_in[2];
    const int*   paths   = (const int*)d_in[3];

    int nL = in_sizes[0];
    int nP = in_sizes[1];
    int E  = in_sizes[2];
    if (nP > MAXP) nP = MAXP;
    if (nL > MAXL) nL = MAXL;

    int wi = 5;
    for (int i = 3; i < n_in; i++) {
        if (in_sizes[i] == 3072) { wi = i; break; }
    }
    const float* K_link = (const float*)d_in[wi + 0];
    const float* R_link = (const float*)d_in[wi + 1];
    const float* b_link = (const float*)d_in[wi + 2];
    const float* K_path = (const float*)d_in[wi + 3];
    const float* R_path = (const float*)d_in[wi + 4];
    const float* b_path = (const float*)d_in[wi + 5];
    const float* W1     = (const float*)d_in[wi + 6];
    const float* b1v    = (const float*)d_in[wi + 7];
    const float* W2     = (const float*)d_in[wi + 8];
    const float* b2v    = (const float*)d_in[wi + 9];
    const float* Wf     = (const float*)d_in[wi + 10];
    const float* bfv    = (const float*)d_in[wi + 11];
    float* out = (float*)d_out;

    cudaFuncSetAttribute(k_readout, cudaFuncAttributeMaxDynamicSharedMemorySize, RO_SMEM_BYTES);

    // launches 0-2: init + ordering  (launch index 3 = first k_path -> ncu target)
    k_init_all<<<(nP * 32 + 255) / 256, 256>>>(cap, traffic, K_path, b_path, nP, nL);
    k_offsets<<<(E + 255) / 256, 256>>>(paths, E, nP);
    k_order_build<<<1, 1024>>>(nP);

    // launches 3-10: T=4 message-passing iterations
    for (int it = 0; it < 4; it++) {
        k_path<<<(nP + 127) / 128, 128>>>(links, R_path, b_path, nP);
        k_link<<<(nL + 63) / 64, 64>>>(K_link, R_link, b_link, K_path, b_path, nL);
    }

    // launch 11: readout
    k_readout<<<(nP + 63) / 64, 256, RO_SMEM_BYTES>>>(W1, b1v, W2, b2v, Wf, bfv, out, nP);
}

// round 7
// speedup vs baseline: 1.7544x; 1.0704x over previous
#include <cuda_runtime.h>

#define MAXP 131072
#define MAXL 16384

typedef unsigned long long u64;

// ---------------- device scratch ----------------
__device__ float g_path_state[MAXP * 32];   // [P,32]
__device__ float g_link_state[MAXL * 32];   // [L,32]
__device__ float g_link_agg[MAXL * 32];     // [L,32] segment-sum accumulator
__device__ float g_lkf[MAXL * 96];          // per-link projected input (z|r|A), biases folded
__device__ int   g_off[MAXP + 1];
__device__ int   g_order[MAXP];

// ---------------- math helpers ----------------
__device__ __forceinline__ float tanhapx_(float x) {
    float y;
    asm("tanh.approx.f32 %0, %1;" : "=f"(y) : "f"(x));
    return y;
}
__device__ __forceinline__ float sigm_(float x) {
    return fmaf(0.5f, tanhapx_(0.5f * x), 0.5f);
}
__device__ __forceinline__ float selu_(float x) {
    const float sc = 1.0507009873554805f, al = 1.6732632423543772f;
    return x > 0.f ? sc * x : sc * al * (__expf(x) - 1.f);
}
__device__ __forceinline__ void redv4(float* gp, float a, float b, float c, float d) {
    asm volatile("red.global.add.v4.f32 [%0], {%1, %2, %3, %4};"
                 :: "l"(gp), "f"(a), "f"(b), "f"(c), "f"(d) : "memory");
}
// ---- packed f32x2 ----
__device__ __forceinline__ u64 pkdup_(float v) {
    u64 r; asm("mov.b64 %0, {%1, %1};" : "=l"(r) : "f"(v)); return r;
}
__device__ __forceinline__ void upk_(u64 v, float& lo, float& hi) {
    asm("mov.b64 {%0, %1}, %2;" : "=f"(lo), "=f"(hi) : "l"(v));
}
__device__ __forceinline__ u64 ffma2_(u64 a, u64 b, u64 c) {
    u64 d; asm("fma.rn.f32x2 %0, %1, %2, %3;" : "=l"(d) : "l"(a), "l"(b), "l"(c)); return d;
}

// ---------------- launch 0: fused init ----------------
__global__ void k_init_all(const float* __restrict__ cap, const float* __restrict__ traffic,
                           const float* __restrict__ K_path, const float* __restrict__ b_path,
                           int nP, int nL)
{
    int i = blockIdx.x * blockDim.x + threadIdx.x;
    if (i < nP * 32) g_path_state[i] = ((i & 31) == 0) ? traffic[i >> 5] : 0.f;
    if (i < nL * 32) { g_link_state[i] = ((i & 31) == 0) ? cap[i >> 5] : 0.f; g_link_agg[i] = 0.f; }
    if (i < nL * 96) {
        int l = i / 96, j = i - l * 96;
        float fold = (j < 64) ? (b_path[j] + b_path[96 + j]) : b_path[j];
        g_lkf[i] = cap[l] * K_path[j] + fold;
    }
}

// ---------------- launch 1: CSR offsets ----------------
__global__ void k_offsets(const int* __restrict__ paths, int E, int nP) {
    int e = blockIdx.x * blockDim.x + threadIdx.x;
    if (e >= E) return;
    int pe = paths[e];
    if (pe < 0 || pe >= nP) return;
    if (e == 0) { g_off[nP] = E; g_off[pe] = 0; }
    else if (paths[e - 1] != pe) g_off[pe] = e;
}

// ---------------- launch 2: ordering, LONGEST length first (1 block) ----------------
__global__ void __launch_bounds__(1024) k_order_build(int nP) {
    __shared__ int scnt[256];
    int tid = threadIdx.x;
    for (int i = tid; i < 256; i += 1024) scnt[i] = 0;
    __syncthreads();
    for (int p = tid; p < nP; p += 1024) {
        int len = g_off[p + 1] - g_off[p];
        len = min(max(len, 0), 255);
        atomicAdd(&scnt[len], 1);
    }
    __syncthreads();
    if (tid == 0) {
        int b = 0;
        for (int i = 255; i >= 0; i--) { int c = scnt[i]; scnt[i] = b; b += c; }
    }
    __syncthreads();
    for (int p = tid; p < nP; p += 1024) {
        int len = g_off[p + 1] - g_off[p];
        len = min(max(len, 0), 255);
        int pos = atomicAdd(&scnt[len], 1);
        if (pos < nP) g_order[pos] = p;
    }
}

// ---------------- launch 3,5,7,9: path scan (FFMA2) ----------------
// h register-resident; x-projection pre-folded in g_lkf (z:0-31 r:32-63 A:64-95).
// Gates computed in 4 j-quarters of 8 (4 f32x2 pairs each of z/r/B accumulators).
__global__ void __launch_bounds__(128, 4) k_path(
    const int* __restrict__ links,
    const float* __restrict__ R, const float* __restrict__ b, int nP)
{
    __shared__ __align__(16) float wR[3072];
    __shared__ __align__(16) float sb1h[32];
    int tid = threadIdx.x;
    for (int i = tid; i < 3072; i += 128) wR[i] = R[i];
    if (tid < 32) sb1h[tid] = b[96 + 64 + tid];

    int idx = blockIdx.x * 128 + tid;
    int p = 0, off = 0, len = 0;
    if (idx < nP) { p = g_order[idx]; off = g_off[p]; len = g_off[p + 1] - off; if (len < 0) len = 0; }
    __syncthreads();
    if (idx >= nP) return;

    float h[32];
    {
        const float4* hp = (const float4*)(g_path_state + p * 32);
#pragma unroll
        for (int q = 0; q < 8; q++) {
            float4 v = hp[q];
            h[4 * q] = v.x; h[4 * q + 1] = v.y; h[4 * q + 2] = v.z; h[4 * q + 3] = v.w;
        }
    }

    int lk = (len > 0) ? __ldg(links + off) : 0;
    {
        const float* Ln = g_lkf + lk * 96;
        asm volatile("prefetch.global.L1 [%0];" :: "l"(Ln));
        asm volatile("prefetch.global.L1 [%0];" :: "l"(Ln + 32));
        asm volatile("prefetch.global.L1 [%0];" :: "l"(Ln + 64));
    }

    for (int s = 0; s < len; s++) {
        int lk_next = (s + 1 < len) ? __ldg(links + off + s + 1) : 0;
        {
            const float* Ln = g_lkf + lk_next * 96;
            asm volatile("prefetch.global.L1 [%0];" :: "l"(Ln));
            asm volatile("prefetch.global.L1 [%0];" :: "l"(Ln + 32));
            asm volatile("prefetch.global.L1 [%0];" :: "l"(Ln + 64));
        }
        const float* Lrow = g_lkf + lk * 96;
        float hn[32];
#pragma unroll
        for (int qrt = 0; qrt < 4; qrt++) {
            const int j0 = qrt * 8;
            u64 az2[4], ar2[4], B2[4];
            float A[8];
            {
                ulonglong2 z01 = *(const ulonglong2*)(Lrow + j0);
                ulonglong2 z23 = *(const ulonglong2*)(Lrow + j0 + 4);
                az2[0] = z01.x; az2[1] = z01.y; az2[2] = z23.x; az2[3] = z23.y;
                ulonglong2 r01 = *(const ulonglong2*)(Lrow + 32 + j0);
                ulonglong2 r23 = *(const ulonglong2*)(Lrow + 32 + j0 + 4);
                ar2[0] = r01.x; ar2[1] = r01.y; ar2[2] = r23.x; ar2[3] = r23.y;
                float4 va0 = *(const float4*)(Lrow + 64 + j0);
                float4 va1 = *(const float4*)(Lrow + 64 + j0 + 4);
                A[0] = va0.x; A[1] = va0.y; A[2] = va0.z; A[3] = va0.w;
                A[4] = va1.x; A[5] = va1.y; A[6] = va1.z; A[7] = va1.w;
                ulonglong2 b01 = *(const ulonglong2*)(sb1h + j0);
                ulonglong2 b23 = *(const ulonglong2*)(sb1h + j0 + 4);
                B2[0] = b01.x; B2[1] = b01.y; B2[2] = b23.x; B2[3] = b23.y;
            }
#pragma unroll 8
            for (int i = 0; i < 32; i++) {
                u64 h2 = pkdup_(h[i]);
                const ulonglong2* wz = (const ulonglong2*)(wR + i * 96 + j0);
                const ulonglong2* wr = (const ulonglong2*)(wR + i * 96 + 32 + j0);
                const ulonglong2* wh = (const ulonglong2*)(wR + i * 96 + 64 + j0);
                ulonglong2 a0 = wz[0], a1 = wz[1];
                az2[0] = ffma2_(h2, a0.x, az2[0]);
                az2[1] = ffma2_(h2, a0.y, az2[1]);
                az2[2] = ffma2_(h2, a1.x, az2[2]);
                az2[3] = ffma2_(h2, a1.y, az2[3]);
                ulonglong2 c0 = wr[0], c1 = wr[1];
                ar2[0] = ffma2_(h2, c0.x, ar2[0]);
                ar2[1] = ffma2_(h2, c0.y, ar2[1]);
                ar2[2] = ffma2_(h2, c1.x, ar2[2]);
                ar2[3] = ffma2_(h2, c1.y, ar2[3]);
                ulonglong2 d0 = wh[0], d1 = wh[1];
                B2[0] = ffma2_(h2, d0.x, B2[0]);
                B2[1] = ffma2_(h2, d0.y, B2[1]);
                B2[2] = ffma2_(h2, d1.x, B2[2]);
                B2[3] = ffma2_(h2, d1.y, B2[3]);
            }
#pragma unroll
            for (int q = 0; q < 4; q++) {
                float zlo, zhi, rlo, rhi, blo, bhi;
                upk_(az2[q], zlo, zhi);
                upk_(ar2[q], rlo, rhi);
                upk_(B2[q], blo, bhi);
                float z0 = sigm_(zlo), z1 = sigm_(zhi);
                float r0 = sigm_(rlo), r1 = sigm_(rhi);
                float hh0 = tanhapx_(A[2 * q] + r0 * blo);
                float hh1 = tanhapx_(A[2 * q + 1] + r1 * bhi);
                hn[j0 + 2 * q]     = z0 * h[j0 + 2 * q]     + (1.f - z0) * hh0;
                hn[j0 + 2 * q + 1] = z1 * h[j0 + 2 * q + 1] + (1.f - z1) * hh1;
            }
        }
        float* agg = g_link_agg + lk * 32;
#pragma unroll
        for (int q = 0; q < 8; q++)
            redv4(agg + 4 * q, hn[4 * q], hn[4 * q + 1], hn[4 * q + 2], hn[4 * q + 3]);
#pragma unroll
        for (int j = 0; j < 32; j++) h[j] = hn[j];
        lk = lk_next;
    }

    float4* ho = (float4*)(g_path_state + p * 32);
#pragma unroll
    for (int q = 0; q < 8; q++)
        ho[q] = make_float4(h[4 * q], h[4 * q + 1], h[4 * q + 2], h[4 * q + 3]);
}

// ---------------- launch 4,6,8,10: link GRU + agg rezero + next-iter LKf ----------------
__global__ void __launch_bounds__(64) k_link(
    const float* __restrict__ K, const float* __restrict__ R, const float* __restrict__ b,
    const float* __restrict__ K_path, const float* __restrict__ b_path, int nL)
{
    __shared__ __align__(16) float wK[3072], wRR[3072], wKp[3072];
    __shared__ __align__(16) float sb0[96], sb1[96], sfold[96];
    int tid = threadIdx.x;
    for (int i = tid; i < 3072; i += 64) { wK[i] = K[i]; wRR[i] = R[i]; wKp[i] = K_path[i]; }
    for (int i = tid; i < 96; i += 64) {
        sb0[i] = b[i]; sb1[i] = b[96 + i];
        sfold[i] = (i < 64) ? (b_path[i] + b_path[96 + i]) : b_path[i];
    }
    int l = blockIdx.x * 64 + tid;
    __syncthreads();
    if (l >= nL) return;

    float x[32], h[32];
    {
        const float4* xp = (const float4*)(g_link_agg + l * 32);
        const float4* hp = (const float4*)(g_link_state + l * 32);
#pragma unroll
        for (int q = 0; q < 8; q++) {
            float4 v = xp[q];
            x[4 * q] = v.x; x[4 * q + 1] = v.y; x[4 * q + 2] = v.z; x[4 * q + 3] = v.w;
            float4 u = hp[q];
            h[4 * q] = u.x; h[4 * q + 1] = u.y; h[4 * q + 2] = u.z; h[4 * q + 3] = u.w;
        }
    }

    float hn[32];
#pragma unroll
    for (int half = 0; half < 2; half++) {
        const int j0 = half * 16;
        float az[16], ar[16], A[16], B[16];
#pragma unroll
        for (int j = 0; j < 16; j++) {
            az[j] = sb0[j0 + j] + sb1[j0 + j];
            ar[j] = sb0[32 + j0 + j] + sb1[32 + j0 + j];
            A[j]  = sb0[64 + j0 + j];
            B[j]  = sb1[64 + j0 + j];
        }
#pragma unroll 2
        for (int i = 0; i < 32; i++) {
            float xi = x[i], hi = h[i];
            const float4* kz = (const float4*)(wK + i * 96 + j0);
            const float4* kr = (const float4*)(wK + i * 96 + 32 + j0);
            const float4* kh = (const float4*)(wK + i * 96 + 64 + j0);
            const float4* rz = (const float4*)(wRR + i * 96 + j0);
            const float4* rr = (const float4*)(wRR + i * 96 + 32 + j0);
            const float4* rh = (const float4*)(wRR + i * 96 + 64 + j0);
#pragma unroll
            for (int q = 0; q < 4; q++) {
                float4 a = kz[q], c = rz[q];
                az[4 * q + 0] = fmaf(xi, a.x, fmaf(hi, c.x, az[4 * q + 0]));
                az[4 * q + 1] = fmaf(xi, a.y, fmaf(hi, c.y, az[4 * q + 1]));
                az[4 * q + 2] = fmaf(xi, a.z, fmaf(hi, c.z, az[4 * q + 2]));
                az[4 * q + 3] = fmaf(xi, a.w, fmaf(hi, c.w, az[4 * q + 3]));
                float4 d = kr[q], e = rr[q];
                ar[4 * q + 0] = fmaf(xi, d.x, fmaf(hi, e.x, ar[4 * q + 0]));
                ar[4 * q + 1] = fmaf(xi, d.y, fmaf(hi, e.y, ar[4 * q + 1]));
                ar[4 * q + 2] = fmaf(xi, d.z, fmaf(hi, e.z, ar[4 * q + 2]));
                ar[4 * q + 3] = fmaf(xi, d.w, fmaf(hi, e.w, ar[4 * q + 3]));
                float4 f = kh[q], g = rh[q];
                A[4 * q + 0] = fmaf(xi, f.x, A[4 * q + 0]);
                A[4 * q + 1] = fmaf(xi, f.y, A[4 * q + 1]);
                A[4 * q + 2] = fmaf(xi, f.z, A[4 * q + 2]);
                A[4 * q + 3] = fmaf(xi, f.w, A[4 * q + 3]);
                B[4 * q + 0] = fmaf(hi, g.x, B[4 * q + 0]);
                B[4 * q + 1] = fmaf(hi, g.y, B[4 * q + 1]);
                B[4 * q + 2] = fmaf(hi, g.z, B[4 * q + 2]);
                B[4 * q + 3] = fmaf(hi, g.w, B[4 * q + 3]);
            }
        }
#pragma unroll
        for (int j = 0; j < 16; j++) {
            float z = sigm_(az[j]);
            float r = sigm_(ar[j]);
            float hh = tanhapx_(A[j] + r * B[j]);
            hn[j0 + j] = z * h[j0 + j] + (1.f - z) * hh;
        }
    }

    {
        float4* ho = (float4*)(g_link_state + l * 32);
        float4* ao = (float4*)(g_link_agg + l * 32);
#pragma unroll
        for (int q = 0; q < 8; q++) {
            ho[q] = make_float4(hn[4 * q], hn[4 * q + 1], hn[4 * q + 2], hn[4 * q + 3]);
            ao[q] = make_float4(0.f, 0.f, 0.f, 0.f);
        }
    }

    float* Lout = g_lkf + l * 96;
#pragma unroll
    for (int c = 0; c < 6; c++) {
        float acc[16];
#pragma unroll
        for (int j = 0; j < 16; j++) acc[j] = sfold[c * 16 + j];
#pragma unroll 4
        for (int i = 0; i < 32; i++) {
            float hi = hn[i];
            const float4* w = (const float4*)(wKp + i * 96 + c * 16);
#pragma unroll
            for (int q = 0; q < 4; q++) {
                float4 a = w[q];
                acc[4 * q + 0] = fmaf(hi, a.x, acc[4 * q + 0]);
                acc[4 * q + 1] = fmaf(hi, a.y, acc[4 * q + 1]);
                acc[4 * q + 2] = fmaf(hi, a.z, acc[4 * q + 2]);
                acc[4 * q + 3] = fmaf(hi, a.w, acc[4 * q + 3]);
            }
        }
#pragma unroll
        for (int q = 0; q < 4; q++)
            *(float4*)(Lout + c * 16 + 4 * q) =
                make_float4(acc[4 * q], acc[4 * q + 1], acc[4 * q + 2], acc[4 * q + 3]);
    }
}

// ---------------- readout (last launch, FFMA2 column-pair scheme) ----------------
// 64 paths/block, 256 threads. Thread (rg,cg): rows r0=4*rg, col pairs c = 2*cg + 32*v.
#define RO_SPS   (32 * 68)
#define RO_SW    (32 * 256)
#define RO_SH    (256 * 68)
#define RO_SMEM_BYTES ((RO_SPS + RO_SW + RO_SH) * 4)

__global__ void __launch_bounds__(256) k_readout(
    const float* __restrict__ W1, const float* __restrict__ b1v,
    const float* __restrict__ W2, const float* __restrict__ b2v,
    const float* __restrict__ Wf, const float* __restrict__ bfv,
    float* __restrict__ out, int nP)
{
    extern __shared__ float sm[];
    float* s_ps = sm;                  // [32][68]
    float* s_w  = sm + RO_SPS;         // [32][256]
    float* s_h  = sm + RO_SPS + RO_SW; // [256][68]

    int tx = threadIdx.x;
    int rg = tx >> 4, cg = tx & 15;
    int r0 = rg * 4;
    int c0 = 2 * cg;                   // base column (pairs c0, c0+1 at +32*v)
    int p0 = blockIdx.x * 64;
    int nrows = nP - p0; if (nrows > 64) nrows = 64;

    for (int idx = tx; idx < 64 * 32; idx += 256) {
        int r = idx >> 5, k = idx & 31;
        float v = (r < nrows) ? g_path_state[(p0 + r) * 32 + k] : 0.f;
        s_ps[k * 68 + r] = v;
    }
    for (int idx = tx; idx < 32 * 256 / 4; idx += 256)
        ((float4*)s_w)[idx] = ((const float4*)W1)[idx];
    __syncthreads();

    // ---- H1 = selu(ps @ W1 + b1) ----
    u64 acc[8][4];
#pragma unroll
    for (int v = 0; v < 8; v++)
#pragma unroll
        for (int u = 0; u < 4; u++) acc[v][u] = 0ull;
    for (int k = 0; k < 32; k++) {
        float4 a = *(const float4*)(s_ps + k * 68 + r0);
        u64 ax = pkdup_(a.x), ay = pkdup_(a.y), az = pkdup_(a.z), aw = pkdup_(a.w);
        const float* wrow = s_w + k * 256 + c0;
#pragma unroll
        for (int v = 0; v < 8; v++) {
            u64 w2 = *(const u64*)(wrow + 32 * v);
            acc[v][0] = ffma2_(ax, w2, acc[v][0]);
            acc[v][1] = ffma2_(ay, w2, acc[v][1]);
            acc[v][2] = ffma2_(az, w2, acc[v][2]);
            acc[v][3] = ffma2_(aw, w2, acc[v][3]);
        }
    }
#pragma unroll
    for (int v = 0; v < 8; v++) {
        float2 bb = *(const float2*)(b1v + c0 + 32 * v);
        float lo[4], hi[4];
#pragma unroll
        for (int u = 0; u < 4; u++) {
            float l_, h_;
            upk_(acc[v][u], l_, h_);
            lo[u] = selu_(l_ + bb.x);
            hi[u] = selu_(h_ + bb.y);
        }
        *(float4*)(s_h + (c0 + 32 * v) * 68 + r0)     = make_float4(lo[0], lo[1], lo[2], lo[3]);
        *(float4*)(s_h + (c0 + 32 * v + 1) * 68 + r0) = make_float4(hi[0], hi[1], hi[2], hi[3]);
    }
    __syncthreads();

    // ---- H2 = selu(H1 @ W2 + b2), K=256 in 8 tiles of 32 ----
    u64 acc2[8][4];
#pragma unroll
    for (int v = 0; v < 8; v++)
#pragma unroll
        for (int u = 0; u < 4; u++) acc2[v][u] = 0ull;
    for (int kt = 0; kt < 8; kt++) {
        for (int idx = tx; idx < 32 * 256 / 4; idx += 256)
            ((float4*)s_w)[idx] = ((const float4*)(W2 + kt * 32 * 256))[idx];
        __syncthreads();
        for (int kk = 0; kk < 32; kk++) {
            int k = kt * 32 + kk;
            float4 a = *(const float4*)(s_h + k * 68 + r0);
            u64 ax = pkdup_(a.x), ay = pkdup_(a.y), az = pkdup_(a.z), aw = pkdup_(a.w);
            const float* wrow = s_w + kk * 256 + c0;
#pragma unroll
            for (int v = 0; v < 8; v++) {
                u64 w2 = *(const u64*)(wrow + 32 * v);
                acc2[v][0] = ffma2_(ax, w2, acc2[v][0]);
                acc2[v][1] = ffma2_(ay, w2, acc2[v][1]);
                acc2[v][2] = ffma2_(az, w2, acc2[v][2]);
                acc2[v][3] = ffma2_(aw, w2, acc2[v][3]);
            }
        }
        __syncthreads();
    }
    // overwrite s_h with H2 (all H1 reads done — synced above)
#pragma unroll
    for (int v = 0; v < 8; v++) {
        float2 bb = *(const float2*)(b2v + c0 + 32 * v);
        float lo[4], hi[4];
#pragma unroll
        for (int u = 0; u < 4; u++) {
            float l_, h_;
            upk_(acc2[v][u], l_, h_);
            lo[u] = selu_(l_ + bb.x);
            hi[u] = selu_(h_ + bb.y);
        }
        *(float4*)(s_h + (c0 + 32 * v) * 68 + r0)     = make_float4(lo[0], lo[1], lo[2], lo[3]);
        *(float4*)(s_h + (c0 + 32 * v + 1) * 68 + r0) = make_float4(hi[0], hi[1], hi[2], hi[3]);
    }
    __syncthreads();

    // ---- pred = concat(H2, ps) @ Wf + bf ----
    if (tx < 128) {
        int p = tx >> 1, o = tx & 1;
        if (p < nrows) {
            float s = bfv[o];
            for (int i = 0; i < 256; i++) s = fmaf(s_h[i * 68 + p], Wf[i * 2 + o], s);
            for (int j = 0; j < 32; j++)  s = fmaf(s_ps[j * 68 + p], Wf[(256 + j) * 2 + o], s);
            out[(p0 + p) * 2 + o] = s;
        }
    }
}

// ---------------- host ----------------
extern "C" void kernel_launch(void* const* d_in, const int* in_sizes, int n_in,
                              void* d_out, int out_size)
{
    const float* cap     = (const float*)d_in[0];
    const float* traffic = (const float*)d_in[1];
    const int*   links   = (const int*)d_in[2];
    const int*   paths   = (const int*)d_in[3];

    int nL = in_sizes[0];
    int nP = in_sizes[1];
    int E  = in_sizes[2];
    if (nP > MAXP) nP = MAXP;
    if (nL > MAXL) nL = MAXL;

    int wi = 5;
    for (int i = 3; i < n_in; i++) {
        if (in_sizes[i] == 3072) { wi = i; break; }
    }
    const float* K_link = (const float*)d_in[wi + 0];
    const float* R_link = (const float*)d_in[wi + 1];
    const float* b_link = (const float*)d_in[wi + 2];
    const float* K_path = (const float*)d_in[wi + 3];
    const float* R_path = (const float*)d_in[wi + 4];
    const float* b_path = (const float*)d_in[wi + 5];
    const float* W1     = (const float*)d_in[wi + 6];
    const float* b1v    = (const float*)d_in[wi + 7];
    const float* W2     = (const float*)d_in[wi + 8];
    const float* b2v    = (const float*)d_in[wi + 9];
    const float* Wf     = (const float*)d_in[wi + 10];
    const float* bfv    = (const float*)d_in[wi + 11];
    float* out = (float*)d_out;

    cudaFuncSetAttribute(k_readout, cudaFuncAttributeMaxDynamicSharedMemorySize, RO_SMEM_BYTES);

    // launches 0-2: init + ordering  (launch index 3 = first k_path -> ncu target)
    k_init_all<<<(nP * 32 + 255) / 256, 256>>>(cap, traffic, K_path, b_path, nP, nL);
    k_offsets<<<(E + 255) / 256, 256>>>(paths, E, nP);
    k_order_build<<<1, 1024>>>(nP);

    // launches 3-10: T=4 message-passing iterations
    for (int it = 0; it < 4; it++) {
        k_path<<<(nP + 127) / 128, 128>>>(links, R_path, b_path, nP);
        k_link<<<(nL + 63) / 64, 64>>>(K_link, R_link, b_link, K_path, b_path, nL);
    }

    // launch 11: readout
    k_readout<<<(nP + 63) / 64, 256, RO_SMEM_BYTES>>>(W1, b1v, W2, b2v, Wf, bfv, out, nP);
}